// round 13
// baseline (speedup 1.0000x reference)
#include <cuda_runtime.h>
#include <cuda_fp16.h>
#include <math.h>
#include <stdint.h>

#define NUC 80000
#define NPC 40000
#define NEC 160000
#define DMC 256
#define NHC 4
#define NDC 64
#define LDPROJ 768

static const size_t SZ_U = (size_t)NUC * DMC;
static const size_t SZ_P = (size_t)NPC * DMC;

// Scratch layout (float units)
static const size_t OFF_XUA   = 0;
static const size_t OFF_XUB   = SZ_U;
static const size_t OFF_XPB   = 2 * SZ_U;
static const size_t OFF_WBIGT = OFF_XPB + SZ_P;                 // fp16 [4][768][256]
static const size_t OFF_BBIG  = OFF_WBIGT + (size_t)4 * LDPROJ * DMC / 2;
static const size_t OFF_WOUTT = OFF_BBIG + 4 * LDPROJ;          // fp16 [4][256][256]
static const size_t OFF_INT   = OFF_WOUTT + (size_t)4 * DMC * DMC / 2;
static const size_t I_ROWP = 0;
static const size_t I_ROWU = I_ROWP + NPC + 1;
static const size_t I_DEGP = I_ROWU + NUC + 1;
static const size_t I_DEGU = I_DEGP + NPC;
static const size_t I_CURP = I_DEGU + NUC;
static const size_t I_CURU = I_CURP + NPC;
static const size_t I_COLP = I_CURU + NUC;
static const size_t I_COLU = I_COLP + NEC;
static const size_t N_INTS = I_COLU + NEC;
static const size_t OFF_H     = (OFF_INT + N_INTS + 3) & ~(size_t)3;
static const size_t H_PROJ16U = OFF_H;
static const size_t H_PROJ16P = H_PROJ16U + (size_t)NUC * LDPROJ / 2;
static const size_t H_XU16A   = H_PROJ16P + (size_t)NPC * LDPROJ / 2;
static const size_t H_XU16B   = H_XU16A + SZ_U / 2;
static const size_t H_XP16A   = H_XU16B + SZ_U / 2;
static const size_t H_XP16B   = H_XP16A + SZ_P / 2;
static const size_t H_AGG16U  = H_XP16B + SZ_P / 2;
static const size_t H_AGG16P  = H_AGG16U + SZ_U / 2;
static const size_t TOTAL_F   = H_AGG16P + SZ_P / 2;

__device__ float g_buf[TOTAL_F];

// ---------------------------------------------------------------------------
__device__ __forceinline__ float gelu_f(float x) {
    return 0.5f * x * (1.0f + erff(x * 0.70710678118654752f));
}
__device__ __forceinline__ uint32_t smem_u32(const void* p) {
    return (uint32_t)__cvta_generic_to_shared(p);
}

#define CP_ASYNC16(dst, src, sz) \
    asm volatile("cp.async.cg.shared.global [%0], [%1], 16, %2;" \
                 :: "r"(dst), "l"(src), "r"(sz) : "memory")
#define CP_COMMIT() asm volatile("cp.async.commit_group;" ::: "memory")
#define CP_WAIT0()  asm volatile("cp.async.wait_group 0;" ::: "memory")

#define LDSM4(r0, r1, r2, r3, addr) \
    asm volatile("ldmatrix.sync.aligned.m8n8.x4.shared.b16 {%0,%1,%2,%3}, [%4];" \
                 : "=r"(r0), "=r"(r1), "=r"(r2), "=r"(r3) : "r"(addr))

#define MMA16(d, av, b0v, b1v) \
    asm volatile("mma.sync.aligned.m16n8k16.row.col.f32.f16.f16.f32 " \
                 "{%0,%1,%2,%3}, {%4,%5,%6,%7}, {%8,%9}, {%0,%1,%2,%3};" \
                 : "+f"((d)[0]), "+f"((d)[1]), "+f"((d)[2]), "+f"((d)[3]) \
                 : "r"((av)[0]), "r"((av)[1]), "r"((av)[2]), "r"((av)[3]), \
                   "r"(b0v), "r"(b1v))

// ---------------------------------------------------------------------------
// Weight assembly (fp16, transposed [n][k])
__global__ void copyq_kernel(const float* __restrict__ Wq, const float* __restrict__ bq,
                             __half* __restrict__ WbigT, float* __restrict__ bbig) {
    int c = blockIdx.x, i = blockIdx.y, j = threadIdx.x;
    WbigT[((size_t)c * LDPROJ + j) * DMC + i] =
        __float2half_rn(Wq[(size_t)c * DMC * DMC + (size_t)i * DMC + j]);
    if (i == 0) bbig[(size_t)c * LDPROJ + j] = bq[(size_t)c * DMC + j];
}

__global__ void fuse_w_kernel(const float* __restrict__ Wk, const float* __restrict__ Wv,
                              const float* __restrict__ arel, const float* __restrict__ mrel,
                              __half* __restrict__ WbigT) {
    int c = blockIdx.x, i = blockIdx.y, j = threadIdx.x;
    int kv = c >> 2, lt = c & 3;
    const float* Wsrc = (kv ? Wv : Wk) + (size_t)lt * DMC * DMC;
    const float* R    = (kv ? mrel : arel) + (size_t)lt * NHC * NDC * NDC;
    int h = j >> 6, e = j & 63;
    const float* wrow = Wsrc + (size_t)i * DMC + h * NDC;
    const float* rr   = R + (size_t)h * NDC * NDC + e;
    float sum = 0.0f;
#pragma unroll 8
    for (int d = 0; d < NDC; d++) sum = fmaf(wrow[d], rr[(size_t)d * NDC], sum);
    int n = DMC + kv * DMC + j;
    WbigT[((size_t)lt * LDPROJ + n) * DMC + i] = __float2half_rn(sum);
}

__global__ void fuse_b_kernel(const float* __restrict__ bk, const float* __restrict__ bv,
                              const float* __restrict__ arel, const float* __restrict__ mrel,
                              float* __restrict__ bbig) {
    int c = blockIdx.x, j = threadIdx.x;
    int kv = c >> 2, lt = c & 3;
    const float* bsrc = (kv ? bv : bk) + (size_t)lt * DMC;
    const float* R    = (kv ? mrel : arel) + (size_t)lt * NHC * NDC * NDC;
    int h = j >> 6, e = j & 63;
    float sum = 0.0f;
#pragma unroll 8
    for (int d = 0; d < NDC; d++)
        sum = fmaf(bsrc[h * NDC + d], R[(size_t)h * NDC * NDC + (size_t)d * NDC + e], sum);
    bbig[(size_t)lt * LDPROJ + DMC + kv * DMC + j] = sum;
}

__global__ void woutT_kernel(const float* __restrict__ Wout, __half* __restrict__ WoutT) {
    int c = blockIdx.x, k = blockIdx.y, n = threadIdx.x;
    WoutT[((size_t)c * DMC + n) * DMC + k] =
        __float2half_rn(Wout[(size_t)c * DMC * DMC + (size_t)k * DMC + n]);
}

// ---------------------------------------------------------------------------
__global__ void gather_kernel(const int* __restrict__ ids, const float* __restrict__ tab,
                              float* __restrict__ out, __half* __restrict__ out16) {
    size_t i = (size_t)blockIdx.x * blockDim.x + threadIdx.x;
    if (i >= (size_t)NUC * (DMC / 4)) return;
    size_t row = i >> 6;
    int c4 = (int)(i & 63);
    float4 v = ((const float4*)(tab + (size_t)ids[row] * DMC))[c4];
    ((float4*)out)[i] = v;
    __half2 h0 = __floats2half2_rn(v.x, v.y);
    __half2 h1 = __floats2half2_rn(v.z, v.w);
    ((uint2*)out16)[i] = make_uint2(*(uint32_t*)&h0, *(uint32_t*)&h1);
}

__global__ void conv16_kernel(const float* __restrict__ src, __half* __restrict__ dst, size_t n4) {
    size_t i = (size_t)blockIdx.x * blockDim.x + threadIdx.x;
    if (i >= n4) return;
    float4 v = ((const float4*)src)[i];
    __half2 h0 = __floats2half2_rn(v.x, v.y);
    __half2 h1 = __floats2half2_rn(v.z, v.w);
    ((uint2*)dst)[i] = make_uint2(*(uint32_t*)&h0, *(uint32_t*)&h1);
}

// ---------------------------------------------------------------------------
// CSR construction
__global__ void count_deg(const int* __restrict__ src, const int* __restrict__ dst,
                          int* __restrict__ degP, int* __restrict__ degU) {
    int e = blockIdx.x * blockDim.x + threadIdx.x;
    if (e >= NEC) return;
    atomicAdd(&degP[dst[e]], 1);
    atomicAdd(&degU[src[e]], 1);
}

__global__ __launch_bounds__(1024)
void scan_kernel(const int* __restrict__ deg, int* __restrict__ rowptr,
                 int* __restrict__ cursor, int n) {
    __shared__ int wsums[32];
    int t = threadIdx.x;
    int lane = t & 31, wid = t >> 5;
    int C = (n + 1023) / 1024;
    int start = t * C; if (start > n) start = n;
    int end = start + C; if (end > n) end = n;
    int s = 0;
    for (int i = start; i < end; i++) s += deg[i];
    int v = s;
#pragma unroll
    for (int o = 1; o < 32; o <<= 1) {
        int u = __shfl_up_sync(0xffffffffu, v, o);
        if (lane >= o) v += u;
    }
    if (lane == 31) wsums[wid] = v;
    __syncthreads();
    if (wid == 0) {
        int wv = wsums[lane];
#pragma unroll
        for (int o = 1; o < 32; o <<= 1) {
            int u = __shfl_up_sync(0xffffffffu, wv, o);
            if (lane >= o) wv += u;
        }
        wsums[lane] = wv;
    }
    __syncthreads();
    int warp_off = (wid > 0) ? wsums[wid - 1] : 0;
    int run = warp_off + v - s;
    for (int i = start; i < end; i++) {
        rowptr[i] = run;
        cursor[i] = run;
        run += deg[i];
    }
    if (t == 0) rowptr[n] = wsums[31];
}

__global__ void build_csr(const int* __restrict__ src, const int* __restrict__ dst,
                          int* __restrict__ curP, int* __restrict__ curU,
                          int* __restrict__ colP, int* __restrict__ colU) {
    int e = blockIdx.x * blockDim.x + threadIdx.x;
    if (e >= NEC) return;
    int s = src[e], d = dst[e];
    colP[atomicAdd(&curP[d], 1)] = s;
    colU[atomicAdd(&curU[s], 1)] = d;
}

// ---------------------------------------------------------------------------
// FP16 GEMM (unchanged from R12)
#define SROW 40
__global__ __launch_bounds__(256, 2)
void gemm_fp16(const __half* __restrict__ A16, const __half* __restrict__ BT,
               const float* __restrict__ bias, float* __restrict__ C, int ldc, int Mtot,
               int mode, const float* __restrict__ xold, const float* __restrict__ skipPtr,
               int gelu_after, __half* __restrict__ C16, int ldc16) {
    __shared__ __half sA[2][128 * SROW];
    __shared__ __half sB[2][128 * SROW];

    const int t = threadIdx.x;
    const int lane = t & 31;
    const int warp = t >> 5;
    const int wm = warp & 3;
    const int wn = warp >> 2;
    const int bm = blockIdx.y * 128;
    const int bn = blockIdx.x * 128;

    const int lr_ = t >> 2, lc_ = t & 3;
    const __half* gA0 = A16 + (size_t)(bm + lr_) * DMC + lc_ * 8;
    const __half* gA1 = A16 + (size_t)(bm + lr_ + 64) * DMC + lc_ * 8;
    const __half* gB0 = BT + (size_t)(bn + lr_) * DMC + lc_ * 8;
    const __half* gB1 = BT + (size_t)(bn + lr_ + 64) * DMC + lc_ * 8;
    const uint32_t szA0 = (bm + lr_ < Mtot) ? 16u : 0u;
    const uint32_t szA1 = (bm + lr_ + 64 < Mtot) ? 16u : 0u;
    uint32_t dA0[2], dA1[2], dB0[2], dB1[2];
#pragma unroll
    for (int b = 0; b < 2; b++) {
        dA0[b] = smem_u32(&sA[b][lr_ * SROW + lc_ * 8]);
        dA1[b] = smem_u32(&sA[b][(lr_ + 64) * SROW + lc_ * 8]);
        dB0[b] = smem_u32(&sB[b][lr_ * SROW + lc_ * 8]);
        dB1[b] = smem_u32(&sB[b][(lr_ + 64) * SROW + lc_ * 8]);
    }

    const int a_row = (lane & 7) + ((lane >> 3) & 1) * 8;
    const int a_ch  = ((lane >> 4) & 1) * 8;
    const int b_row = (lane & 7) + ((lane >> 4) & 1) * 8;
    const int b_ch  = ((lane >> 3) & 1) * 8;

    float acc[2][8][4];
#pragma unroll
    for (int mi = 0; mi < 2; mi++)
#pragma unroll
        for (int ni = 0; ni < 8; ni++)
#pragma unroll
            for (int r = 0; r < 4; r++) acc[mi][ni][r] = 0.0f;

    CP_ASYNC16(dA0[0], gA0, szA0);
    CP_ASYNC16(dA1[0], gA1, szA1);
    CP_ASYNC16(dB0[0], gB0, 16u);
    CP_ASYNC16(dB1[0], gB1, 16u);
    CP_COMMIT();

    for (int i = 0; i < 8; i++) {
        CP_WAIT0();
        __syncthreads();
        if (i < 7) {
            const int kn = (i + 1) * 32;
            const int nb = (i + 1) & 1;
            CP_ASYNC16(dA0[nb], gA0 + kn, szA0);
            CP_ASYNC16(dA1[nb], gA1 + kn, szA1);
            CP_ASYNC16(dB0[nb], gB0 + kn, 16u);
            CP_ASYNC16(dB1[nb], gB1 + kn, 16u);
            CP_COMMIT();
        }
        const int cb = i & 1;
#pragma unroll
        for (int ks = 0; ks < 2; ks++) {
            uint32_t a[2][4], b[8][2];
#pragma unroll
            for (int mi = 0; mi < 2; mi++) {
                uint32_t addr = smem_u32(&sA[cb][(wm * 32 + mi * 16 + a_row) * SROW + ks * 16 + a_ch]);
                LDSM4(a[mi][0], a[mi][1], a[mi][2], a[mi][3], addr);
            }
#pragma unroll
            for (int n2 = 0; n2 < 4; n2++) {
                uint32_t addr = smem_u32(&sB[cb][(wn * 64 + n2 * 16 + b_row) * SROW + ks * 16 + b_ch]);
                LDSM4(b[2 * n2][0], b[2 * n2][1], b[2 * n2 + 1][0], b[2 * n2 + 1][1], addr);
            }
#pragma unroll
            for (int mi = 0; mi < 2; mi++)
#pragma unroll
                for (int ni = 0; ni < 8; ni++)
                    MMA16(acc[mi][ni], a[mi], b[ni][0], b[ni][1]);
        }
    }

    float beta = 1.0f, omb = 0.0f;
    if (mode == 1) {
        float sv = *skipPtr;
        beta = 1.0f / (1.0f + expf(-sv));
        omb = 1.0f - beta;
    }

    const int rg = lane >> 2;
    const int cg = (lane & 3) * 2;
#pragma unroll
    for (int mi = 0; mi < 2; mi++) {
#pragma unroll
        for (int ni = 0; ni < 8; ni++) {
            int col = bn + wn * 64 + ni * 8 + cg;
            float2 bb = *(const float2*)(bias + col);
#pragma unroll
            for (int half = 0; half < 2; half++) {
                int row = bm + wm * 32 + mi * 16 + rg + half * 8;
                if (row >= Mtot) continue;
                float v0 = acc[mi][ni][half * 2 + 0] + bb.x;
                float v1 = acc[mi][ni][half * 2 + 1] + bb.y;
                if (mode == 1) {
                    float2 xo = *(const float2*)(xold + (size_t)row * DMC + col);
                    v0 = beta * v0 + omb * xo.x;
                    v1 = beta * v1 + omb * xo.y;
                }
                if (gelu_after) { v0 = gelu_f(v0); v1 = gelu_f(v1); }
                if (C)
                    *(float2*)(C + (size_t)row * ldc + col) = make_float2(v0, v1);
                if (C16) {
                    __half2 hv = __floats2half2_rn(v0, v1);
                    *(uint32_t*)(C16 + (size_t)row * ldc16 + col) = *(uint32_t*)&hv;
                }
            }
        }
    }
}

// ---------------------------------------------------------------------------
// Fused edge attention, one warp per dst, 4 heads in-warp.
// Fast path deg<=8: software-pipelined (all loads issued before consumption).
__device__ __forceinline__ float dot8(const uint4& ua, const float* qx) {
    float2 a0 = __half22float2(*(const __half2*)&ua.x);
    float2 a1 = __half22float2(*(const __half2*)&ua.y);
    float2 a2 = __half22float2(*(const __half2*)&ua.z);
    float2 a3 = __half22float2(*(const __half2*)&ua.w);
    float p = qx[0] * a0.x + qx[1] * a0.y;
    p = fmaf(qx[2], a1.x, p); p = fmaf(qx[3], a1.y, p);
    p = fmaf(qx[4], a2.x, p); p = fmaf(qx[5], a2.y, p);
    p = fmaf(qx[6], a3.x, p); p = fmaf(qx[7], a3.y, p);
    return p;
}

__global__ __launch_bounds__(256)
void agg_kernel(const int* __restrict__ rowptr, const int* __restrict__ col,
                const __half* __restrict__ q, const __half* __restrict__ kt,
                const __half* __restrict__ vt, const float* __restrict__ prel,
                __half* __restrict__ agg16, int ndst) {
    int gid = blockIdx.x * blockDim.x + threadIdx.x;
    int dN = gid >> 5;
    int lane = gid & 31;
    if (dN >= ndst) return;
    const int sub = lane & 7;

    int base = rowptr[dN];
    int deg = rowptr[dN + 1] - base;

    float acc[8] = {0.f, 0.f, 0.f, 0.f, 0.f, 0.f, 0.f, 0.f};
    if (deg > 0) {
        const size_t loff = (size_t)lane * 8;
        float qx[8];
        {
            uint4 uq = *(const uint4*)(q + (size_t)dN * LDPROJ + loff);
            float2 t0 = __half22float2(*(const __half2*)&uq.x);
            float2 t1 = __half22float2(*(const __half2*)&uq.y);
            float2 t2 = __half22float2(*(const __half2*)&uq.z);
            float2 t3 = __half22float2(*(const __half2*)&uq.w);
            qx[0] = t0.x; qx[1] = t0.y; qx[2] = t1.x; qx[3] = t1.y;
            qx[4] = t2.x; qx[5] = t2.y; qx[6] = t3.x; qx[7] = t3.y;
        }
        float pr = prel[lane >> 3] * 0.125f;

        if (deg <= 8) {
            // Phase 1: issue all neighbor-index + kt loads (MLP = deg)
            int scol[8];
#pragma unroll
            for (int j = 0; j < 8; j++)
                scol[j] = (j < deg) ? col[base + j] : 0;
            uint4 uk[8];
#pragma unroll
            for (int j = 0; j < 8; j++)
                if (j < deg)
                    uk[j] = *(const uint4*)(kt + (size_t)scol[j] * LDPROJ + loff);

            // Phase 2: independent dot+reduce trees (interleaved by scheduler)
            float pj[8];
#pragma unroll
            for (int j = 0; j < 8; j++)
                if (j < deg) pj[j] = dot8(uk[j], qx);
#pragma unroll
            for (int o = 4; o > 0; o >>= 1) {
#pragma unroll
                for (int j = 0; j < 8; j++)
                    if (j < deg) pj[j] += __shfl_xor_sync(0xffffffffu, pj[j], o);
            }

            // Phase 3: softmax over the <=8 logits
            float m = -INFINITY;
            float lgsel = -INFINITY;
#pragma unroll
            for (int j = 0; j < 8; j++) {
                if (j < deg) {
                    float lg = pj[j] * pr;
                    pj[j] = lg;
                    m = fmaxf(m, lg);
                    if (j == sub) lgsel = lg;
                }
            }
            float e0 = (sub < deg) ? expf(lgsel - m) : 0.0f;
            float tsum = e0;
#pragma unroll
            for (int o = 4; o > 0; o >>= 1) tsum += __shfl_xor_sync(0xffffffffu, tsum, o);
            float inv = 1.0f / (tsum + 1e-16f);

            // Phase 4: issue all vt loads, then accumulate
            uint4 uv[8];
#pragma unroll
            for (int j = 0; j < 8; j++)
                if (j < deg)
                    uv[j] = *(const uint4*)(vt + (size_t)scol[j] * LDPROJ + loff);
#pragma unroll
            for (int j = 0; j < 8; j++) {
                if (j < deg) {
                    float a = __shfl_sync(0xffffffffu, e0, (lane & 24) | j) * inv;
                    float2 v0 = __half22float2(*(const __half2*)&uv[j].x);
                    float2 v1 = __half22float2(*(const __half2*)&uv[j].y);
                    float2 v2 = __half22float2(*(const __half2*)&uv[j].z);
                    float2 v3 = __half22float2(*(const __half2*)&uv[j].w);
                    acc[0] = fmaf(a, v0.x, acc[0]); acc[1] = fmaf(a, v0.y, acc[1]);
                    acc[2] = fmaf(a, v1.x, acc[2]); acc[3] = fmaf(a, v1.y, acc[3]);
                    acc[4] = fmaf(a, v2.x, acc[4]); acc[5] = fmaf(a, v2.y, acc[5]);
                    acc[6] = fmaf(a, v3.x, acc[6]); acc[7] = fmaf(a, v3.y, acc[7]);
                }
            }
        } else {
            // recompute path (any degree)
            float m = -INFINITY;
            for (int j = 0; j < deg; j++) {
                int s = col[base + j];
                uint4 uk = *(const uint4*)(kt + (size_t)s * LDPROJ + loff);
                float p = dot8(uk, qx);
#pragma unroll
                for (int o = 4; o > 0; o >>= 1) p += __shfl_xor_sync(0xffffffffu, p, o);
                m = fmaxf(m, p * pr);
            }
            float ssum = 0.0f;
            for (int j = 0; j < deg; j++) {
                int s = col[base + j];
                uint4 uk = *(const uint4*)(kt + (size_t)s * LDPROJ + loff);
                float p = dot8(uk, qx);
#pragma unroll
                for (int o = 4; o > 0; o >>= 1) p += __shfl_xor_sync(0xffffffffu, p, o);
                ssum += expf(p * pr - m);
            }
            float inv = 1.0f / (ssum + 1e-16f);
            for (int j = 0; j < deg; j++) {
                int s = col[base + j];
                uint4 uk = *(const uint4*)(kt + (size_t)s * LDPROJ + loff);
                float p = dot8(uk, qx);
#pragma unroll
                for (int o = 4; o > 0; o >>= 1) p += __shfl_xor_sync(0xffffffffu, p, o);
                float a = expf(p * pr - m) * inv;
                uint4 uv = *(const uint4*)(vt + (size_t)s * LDPROJ + loff);
                float2 v0 = __half22float2(*(const __half2*)&uv.x);
                float2 v1 = __half22float2(*(const __half2*)&uv.y);
                float2 v2 = __half22float2(*(const __half2*)&uv.z);
                float2 v3 = __half22float2(*(const __half2*)&uv.w);
                acc[0] = fmaf(a, v0.x, acc[0]); acc[1] = fmaf(a, v0.y, acc[1]);
                acc[2] = fmaf(a, v1.x, acc[2]); acc[3] = fmaf(a, v1.y, acc[3]);
                acc[4] = fmaf(a, v2.x, acc[4]); acc[5] = fmaf(a, v2.y, acc[5]);
                acc[6] = fmaf(a, v3.x, acc[6]); acc[7] = fmaf(a, v3.y, acc[7]);
            }
        }
    }
    __half2 h0 = __floats2half2_rn(gelu_f(acc[0]), gelu_f(acc[1]));
    __half2 h1 = __floats2half2_rn(gelu_f(acc[2]), gelu_f(acc[3]));
    __half2 h2 = __floats2half2_rn(gelu_f(acc[4]), gelu_f(acc[5]));
    __half2 h3 = __floats2half2_rn(gelu_f(acc[6]), gelu_f(acc[7]));
    uint4 out = make_uint4(*(uint32_t*)&h0, *(uint32_t*)&h1, *(uint32_t*)&h2, *(uint32_t*)&h3);
    *(uint4*)(agg16 + (size_t)dN * DMC + (size_t)lane * 8) = out;
}

// ---------------------------------------------------------------------------
extern "C" void kernel_launch(void* const* d_in, const int* in_sizes, int n_in,
                              void* d_out, int out_size) {
    (void)in_sizes; (void)n_in; (void)out_size;

    float* base = nullptr;
    cudaGetSymbolAddress((void**)&base, g_buf);

    const int*   user_ids  = (const int*)d_in[0];
    const float* x_product = (const float*)d_in[1];
    const int*   edge_src  = (const int*)d_in[2];
    const int*   edge_dst  = (const int*)d_in[3];
    const float* emb       = (const float*)d_in[4];
    const float* Wk        = (const float*)d_in[5];
    const float* bk        = (const float*)d_in[6];
    const float* Wq        = (const float*)d_in[7];
    const float* bq        = (const float*)d_in[8];
    const float* Wv        = (const float*)d_in[9];
    const float* bv        = (const float*)d_in[10];
    const float* Wout      = (const float*)d_in[11];
    const float* bout      = (const float*)d_in[12];
    const float* skipp     = (const float*)d_in[13];
    const float* arel      = (const float*)d_in[14];
    const float* mrel      = (const float*)d_in[15];
    const float* prel      = (const float*)d_in[16];

    float*  xuA     = base + OFF_XUA;
    float*  xuB     = base + OFF_XUB;
    float*  xpB     = base + OFF_XPB;
    __half* WbigT   = (__half*)(base + OFF_WBIGT);
    float*  bbig    = base + OFF_BBIG;
    __half* WoutT   = (__half*)(base + OFF_WOUTT);
    __half* proj16U = (__half*)(base + H_PROJ16U);
    __half* proj16P = (__half*)(base + H_PROJ16P);
    __half* xu16A   = (__half*)(base + H_XU16A);
    __half* xu16B   = (__half*)(base + H_XU16B);
    __half* xp16A   = (__half*)(base + H_XP16A);
    __half* xp16B   = (__half*)(base + H_XP16B);
    __half* agg16U  = (__half*)(base + H_AGG16U);
    __half* agg16P  = (__half*)(base + H_AGG16P);

    int* ibase   = (int*)(base + OFF_INT);
    int* rowptrP = ibase + I_ROWP;
    int* rowptrU = ibase + I_ROWU;
    int* degP    = ibase + I_DEGP;
    int* degU    = ibase + I_DEGU;
    int* curP    = ibase + I_CURP;
    int* curU    = ibase + I_CURU;
    int* colP    = ibase + I_COLP;
    int* colU    = ibase + I_COLU;

    float* out_xu = (float*)d_out;
    float* out_xp = (float*)d_out + SZ_U;

    // 1. Weight assembly
    copyq_kernel<<<dim3(4, 256), 256>>>(Wq, bq, WbigT, bbig);
    fuse_w_kernel<<<dim3(8, 256), 256>>>(Wk, Wv, arel, mrel, WbigT);
    fuse_b_kernel<<<8, 256>>>(bk, bv, arel, mrel, bbig);
    woutT_kernel<<<dim3(4, 256), 256>>>(Wout, WoutT);

    // 2. Gather users (fp32 + fp16); convert products to fp16
    {
        size_t n = (size_t)NUC * (DMC / 4);
        gather_kernel<<<(unsigned)((n + 255) / 256), 256>>>(user_ids, emb, xuA, xu16A);
        size_t n4 = SZ_P / 4;
        conv16_kernel<<<(unsigned)((n4 + 255) / 256), 256>>>(x_product, xp16A, n4);
    }

    // 3. CSRs
    cudaMemsetAsync(degP, 0, (size_t)NPC * sizeof(int));
    cudaMemsetAsync(degU, 0, (size_t)NUC * sizeof(int));
    count_deg<<<(NEC + 255) / 256, 256>>>(edge_src, edge_dst, degP, degU);
    scan_kernel<<<1, 1024>>>(degP, rowptrP, curP, NPC);
    scan_kernel<<<1, 1024>>>(degU, rowptrU, curU, NUC);
    build_csr<<<(NEC + 255) / 256, 256>>>(edge_src, edge_dst, curP, curU, colP, colU);

    const unsigned gyU = (NUC + 127) / 128;
    const unsigned gyP = (NPC + 127) / 128;

    for (int l = 0; l < 2; l++) {
        const __half* xu16_in = l ? xu16B : xu16A;
        const __half* xp16_in = l ? xp16B : xp16A;
        const float*  xu_in   = l ? xuB : xuA;
        const float*  xp_in   = l ? xpB : x_product;
        float* xu_out = l ? out_xu : xuB;
        float* xp_out = l ? out_xp : xpB;
        __half* xu16_out = l ? nullptr : xu16B;
        __half* xp16_out = l ? nullptr : xp16B;
        int gelu_after = (l == 0) ? 1 : 0;

        // Projections: fp16-only outputs
        {
            size_t cu = (size_t)(l * 2 + 0), cp = (size_t)(l * 2 + 1);
            gemm_fp16<<<dim3(LDPROJ / 128, gyU), 256>>>(
                xu16_in, WbigT + cu * LDPROJ * DMC, bbig + cu * LDPROJ,
                nullptr, 0, NUC, 0, nullptr, nullptr, 0, proj16U, LDPROJ);
            gemm_fp16<<<dim3(LDPROJ / 128, gyP), 256>>>(
                xp16_in, WbigT + cp * LDPROJ * DMC, bbig + cp * LDPROJ,
                nullptr, 0, NPC, 0, nullptr, nullptr, 0, proj16P, LDPROJ);
        }

        // Edge attention: one warp per dst, all heads in-warp
        {
            unsigned blocks = (unsigned)(((size_t)NPC * 32 + 255) / 256);
            agg_kernel<<<blocks, 256>>>(rowptrP, colP,
                                        proj16P, proj16U + DMC, proj16U + 2 * DMC,
                                        prel + (size_t)(l * 2 + 0) * NHC, agg16P, NPC);
            blocks = (unsigned)(((size_t)NUC * 32 + 255) / 256);
            agg_kernel<<<blocks, 256>>>(rowptrU, colU,
                                        proj16U, proj16P + DMC, proj16P + 2 * DMC,
                                        prel + (size_t)(l * 2 + 1) * NHC, agg16U, NUC);
        }

        // Output GEMMs with skip blend (+ inter-layer gelu for l==0)
        {
            gemm_fp16<<<dim3(DMC / 128, gyP), 256>>>(
                agg16P, WoutT + (size_t)(l * 2 + 1) * DMC * DMC, bout + (size_t)(l * 2 + 1) * DMC,
                xp_out, DMC, NPC, 1, xp_in, skipp + (l * 2 + 1), gelu_after, xp16_out, DMC);
            gemm_fp16<<<dim3(DMC / 128, gyU), 256>>>(
                agg16U, WoutT + (size_t)(l * 2 + 0) * DMC * DMC, bout + (size_t)(l * 2 + 0) * DMC,
                xu_out, DMC, NUC, 1, xu_in, skipp + (l * 2 + 0), gelu_after, xu16_out, DMC);
        }
    }
}

// round 14
// speedup vs baseline: 1.0883x; 1.0883x over previous
#include <cuda_runtime.h>
#include <cuda_fp16.h>
#include <math.h>
#include <stdint.h>

#define NUC 80000
#define NPC 40000
#define NEC 160000
#define DMC 256
#define NHC 4
#define NDC 64
#define LDPROJ 768

static const size_t SZ_U = (size_t)NUC * DMC;
static const size_t SZ_P = (size_t)NPC * DMC;

// Scratch layout (float units)
static const size_t OFF_WBIGT = 0;                              // fp16 [4][768][256]
static const size_t OFF_BBIG  = OFF_WBIGT + (size_t)4 * LDPROJ * DMC / 2;
static const size_t OFF_WOUTT = OFF_BBIG + 4 * LDPROJ;          // fp16 [4][256][256]
static const size_t OFF_INT   = OFF_WOUTT + (size_t)4 * DMC * DMC / 2;
static const size_t I_ROWP = 0;
static const size_t I_ROWU = I_ROWP + NPC + 1;
static const size_t I_DEGP = I_ROWU + NUC + 1;
static const size_t I_DEGU = I_DEGP + NPC;
static const size_t I_CURP = I_DEGU + NUC;
static const size_t I_CURU = I_CURP + NPC;
static const size_t I_COLP = I_CURU + NUC;
static const size_t I_COLU = I_COLP + NEC;
static const size_t N_INTS = I_COLU + NEC;
static const size_t OFF_H     = (OFF_INT + N_INTS + 3) & ~(size_t)3;
static const size_t H_PROJ16U = OFF_H;
static const size_t H_PROJ16P = H_PROJ16U + (size_t)NUC * LDPROJ / 2;
static const size_t H_XU16A   = H_PROJ16P + (size_t)NPC * LDPROJ / 2;
static const size_t H_XU16B   = H_XU16A + SZ_U / 2;
static const size_t H_XP16A   = H_XU16B + SZ_U / 2;
static const size_t H_XP16B   = H_XP16A + SZ_P / 2;
static const size_t H_AGG16U  = H_XP16B + SZ_P / 2;
static const size_t H_AGG16P  = H_AGG16U + SZ_U / 2;
static const size_t TOTAL_F   = H_AGG16P + SZ_P / 2;

__device__ float g_buf[TOTAL_F];

// ---------------------------------------------------------------------------
__device__ __forceinline__ float gelu_f(float x) {
    return 0.5f * x * (1.0f + erff(x * 0.70710678118654752f));
}
__device__ __forceinline__ uint32_t smem_u32(const void* p) {
    return (uint32_t)__cvta_generic_to_shared(p);
}

#define CP_ASYNC16(dst, src, sz) \
    asm volatile("cp.async.cg.shared.global [%0], [%1], 16, %2;" \
                 :: "r"(dst), "l"(src), "r"(sz) : "memory")
#define CP_COMMIT() asm volatile("cp.async.commit_group;" ::: "memory")
#define CP_WAIT0()  asm volatile("cp.async.wait_group 0;" ::: "memory")

#define LDSM4(r0, r1, r2, r3, addr) \
    asm volatile("ldmatrix.sync.aligned.m8n8.x4.shared.b16 {%0,%1,%2,%3}, [%4];" \
                 : "=r"(r0), "=r"(r1), "=r"(r2), "=r"(r3) : "r"(addr))

#define MMA16(d, av, b0v, b1v) \
    asm volatile("mma.sync.aligned.m16n8k16.row.col.f32.f16.f16.f32 " \
                 "{%0,%1,%2,%3}, {%4,%5,%6,%7}, {%8,%9}, {%0,%1,%2,%3};" \
                 : "+f"((d)[0]), "+f"((d)[1]), "+f"((d)[2]), "+f"((d)[3]) \
                 : "r"((av)[0]), "r"((av)[1]), "r"((av)[2]), "r"((av)[3]), \
                   "r"(b0v), "r"(b1v))

// ---------------------------------------------------------------------------
// Weight assembly (fp16, transposed [n][k])
__global__ void copyq_kernel(const float* __restrict__ Wq, const float* __restrict__ bq,
                             __half* __restrict__ WbigT, float* __restrict__ bbig) {
    int c = blockIdx.x, i = blockIdx.y, j = threadIdx.x;
    WbigT[((size_t)c * LDPROJ + j) * DMC + i] =
        __float2half_rn(Wq[(size_t)c * DMC * DMC + (size_t)i * DMC + j]);
    if (i == 0) bbig[(size_t)c * LDPROJ + j] = bq[(size_t)c * DMC + j];
}

__global__ void fuse_w_kernel(const float* __restrict__ Wk, const float* __restrict__ Wv,
                              const float* __restrict__ arel, const float* __restrict__ mrel,
                              __half* __restrict__ WbigT) {
    int c = blockIdx.x, i = blockIdx.y, j = threadIdx.x;
    int kv = c >> 2, lt = c & 3;
    const float* Wsrc = (kv ? Wv : Wk) + (size_t)lt * DMC * DMC;
    const float* R    = (kv ? mrel : arel) + (size_t)lt * NHC * NDC * NDC;
    int h = j >> 6, e = j & 63;
    const float* wrow = Wsrc + (size_t)i * DMC + h * NDC;
    const float* rr   = R + (size_t)h * NDC * NDC + e;
    float sum = 0.0f;
#pragma unroll 8
    for (int d = 0; d < NDC; d++) sum = fmaf(wrow[d], rr[(size_t)d * NDC], sum);
    int n = DMC + kv * DMC + j;
    WbigT[((size_t)lt * LDPROJ + n) * DMC + i] = __float2half_rn(sum);
}

__global__ void fuse_b_kernel(const float* __restrict__ bk, const float* __restrict__ bv,
                              const float* __restrict__ arel, const float* __restrict__ mrel,
                              float* __restrict__ bbig) {
    int c = blockIdx.x, j = threadIdx.x;
    int kv = c >> 2, lt = c & 3;
    const float* bsrc = (kv ? bv : bk) + (size_t)lt * DMC;
    const float* R    = (kv ? mrel : arel) + (size_t)lt * NHC * NDC * NDC;
    int h = j >> 6, e = j & 63;
    float sum = 0.0f;
#pragma unroll 8
    for (int d = 0; d < NDC; d++)
        sum = fmaf(bsrc[h * NDC + d], R[(size_t)h * NDC * NDC + (size_t)d * NDC + e], sum);
    bbig[(size_t)lt * LDPROJ + DMC + kv * DMC + j] = sum;
}

__global__ void woutT_kernel(const float* __restrict__ Wout, __half* __restrict__ WoutT) {
    int c = blockIdx.x, k = blockIdx.y, n = threadIdx.x;
    WoutT[((size_t)c * DMC + n) * DMC + k] =
        __float2half_rn(Wout[(size_t)c * DMC * DMC + (size_t)k * DMC + n]);
}

// ---------------------------------------------------------------------------
// Gather user embeddings -> fp16 only
__global__ void gather_kernel(const int* __restrict__ ids, const float* __restrict__ tab,
                              __half* __restrict__ out16) {
    size_t i = (size_t)blockIdx.x * blockDim.x + threadIdx.x;
    if (i >= (size_t)NUC * (DMC / 4)) return;
    size_t row = i >> 6;
    int c4 = (int)(i & 63);
    float4 v = ((const float4*)(tab + (size_t)ids[row] * DMC))[c4];
    __half2 h0 = __floats2half2_rn(v.x, v.y);
    __half2 h1 = __floats2half2_rn(v.z, v.w);
    ((uint2*)out16)[i] = make_uint2(*(uint32_t*)&h0, *(uint32_t*)&h1);
}

__global__ void conv16_kernel(const float* __restrict__ src, __half* __restrict__ dst, size_t n4) {
    size_t i = (size_t)blockIdx.x * blockDim.x + threadIdx.x;
    if (i >= n4) return;
    float4 v = ((const float4*)src)[i];
    __half2 h0 = __floats2half2_rn(v.x, v.y);
    __half2 h1 = __floats2half2_rn(v.z, v.w);
    ((uint2*)dst)[i] = make_uint2(*(uint32_t*)&h0, *(uint32_t*)&h1);
}

// ---------------------------------------------------------------------------
// CSR construction
__global__ void count_deg(const int* __restrict__ src, const int* __restrict__ dst,
                          int* __restrict__ degP, int* __restrict__ degU) {
    int e = blockIdx.x * blockDim.x + threadIdx.x;
    if (e >= NEC) return;
    atomicAdd(&degP[dst[e]], 1);
    atomicAdd(&degU[src[e]], 1);
}

__global__ __launch_bounds__(1024)
void scan_kernel(const int* __restrict__ deg, int* __restrict__ rowptr,
                 int* __restrict__ cursor, int n) {
    __shared__ int wsums[32];
    int t = threadIdx.x;
    int lane = t & 31, wid = t >> 5;
    int C = (n + 1023) / 1024;
    int start = t * C; if (start > n) start = n;
    int end = start + C; if (end > n) end = n;
    int s = 0;
    for (int i = start; i < end; i++) s += deg[i];
    int v = s;
#pragma unroll
    for (int o = 1; o < 32; o <<= 1) {
        int u = __shfl_up_sync(0xffffffffu, v, o);
        if (lane >= o) v += u;
    }
    if (lane == 31) wsums[wid] = v;
    __syncthreads();
    if (wid == 0) {
        int wv = wsums[lane];
#pragma unroll
        for (int o = 1; o < 32; o <<= 1) {
            int u = __shfl_up_sync(0xffffffffu, wv, o);
            if (lane >= o) wv += u;
        }
        wsums[lane] = wv;
    }
    __syncthreads();
    int warp_off = (wid > 0) ? wsums[wid - 1] : 0;
    int run = warp_off + v - s;
    for (int i = start; i < end; i++) {
        rowptr[i] = run;
        cursor[i] = run;
        run += deg[i];
    }
    if (t == 0) rowptr[n] = wsums[31];
}

__global__ void build_csr(const int* __restrict__ src, const int* __restrict__ dst,
                          int* __restrict__ curP, int* __restrict__ curU,
                          int* __restrict__ colP, int* __restrict__ colU) {
    int e = blockIdx.x * blockDim.x + threadIdx.x;
    if (e >= NEC) return;
    int s = src[e], d = dst[e];
    colP[atomicAdd(&curP[d], 1)] = s;
    colU[atomicAdd(&curU[s], 1)] = d;
}

// ---------------------------------------------------------------------------
// FP16 GEMM, cp.async double-buffer + ldmatrix + m16n8k16.
// mode 1 skip-blend reads xold16 (fp16, stride DMC).
#define SROW 40
__global__ __launch_bounds__(256, 2)
void gemm_fp16(const __half* __restrict__ A16, const __half* __restrict__ BT,
               const float* __restrict__ bias, float* __restrict__ C, int ldc, int Mtot,
               int mode, const __half* __restrict__ xold16, const float* __restrict__ skipPtr,
               int gelu_after, __half* __restrict__ C16, int ldc16) {
    __shared__ __half sA[2][128 * SROW];
    __shared__ __half sB[2][128 * SROW];

    const int t = threadIdx.x;
    const int lane = t & 31;
    const int warp = t >> 5;
    const int wm = warp & 3;
    const int wn = warp >> 2;
    const int bm = blockIdx.y * 128;
    const int bn = blockIdx.x * 128;

    const int lr_ = t >> 2, lc_ = t & 3;
    const __half* gA0 = A16 + (size_t)(bm + lr_) * DMC + lc_ * 8;
    const __half* gA1 = A16 + (size_t)(bm + lr_ + 64) * DMC + lc_ * 8;
    const __half* gB0 = BT + (size_t)(bn + lr_) * DMC + lc_ * 8;
    const __half* gB1 = BT + (size_t)(bn + lr_ + 64) * DMC + lc_ * 8;
    const uint32_t szA0 = (bm + lr_ < Mtot) ? 16u : 0u;
    const uint32_t szA1 = (bm + lr_ + 64 < Mtot) ? 16u : 0u;
    uint32_t dA0[2], dA1[2], dB0[2], dB1[2];
#pragma unroll
    for (int b = 0; b < 2; b++) {
        dA0[b] = smem_u32(&sA[b][lr_ * SROW + lc_ * 8]);
        dA1[b] = smem_u32(&sA[b][(lr_ + 64) * SROW + lc_ * 8]);
        dB0[b] = smem_u32(&sB[b][lr_ * SROW + lc_ * 8]);
        dB1[b] = smem_u32(&sB[b][(lr_ + 64) * SROW + lc_ * 8]);
    }

    const int a_row = (lane & 7) + ((lane >> 3) & 1) * 8;
    const int a_ch  = ((lane >> 4) & 1) * 8;
    const int b_row = (lane & 7) + ((lane >> 4) & 1) * 8;
    const int b_ch  = ((lane >> 3) & 1) * 8;

    float acc[2][8][4];
#pragma unroll
    for (int mi = 0; mi < 2; mi++)
#pragma unroll
        for (int ni = 0; ni < 8; ni++)
#pragma unroll
            for (int r = 0; r < 4; r++) acc[mi][ni][r] = 0.0f;

    CP_ASYNC16(dA0[0], gA0, szA0);
    CP_ASYNC16(dA1[0], gA1, szA1);
    CP_ASYNC16(dB0[0], gB0, 16u);
    CP_ASYNC16(dB1[0], gB1, 16u);
    CP_COMMIT();

    for (int i = 0; i < 8; i++) {
        CP_WAIT0();
        __syncthreads();
        if (i < 7) {
            const int kn = (i + 1) * 32;
            const int nb = (i + 1) & 1;
            CP_ASYNC16(dA0[nb], gA0 + kn, szA0);
            CP_ASYNC16(dA1[nb], gA1 + kn, szA1);
            CP_ASYNC16(dB0[nb], gB0 + kn, 16u);
            CP_ASYNC16(dB1[nb], gB1 + kn, 16u);
            CP_COMMIT();
        }
        const int cb = i & 1;
#pragma unroll
        for (int ks = 0; ks < 2; ks++) {
            uint32_t a[2][4], b[8][2];
#pragma unroll
            for (int mi = 0; mi < 2; mi++) {
                uint32_t addr = smem_u32(&sA[cb][(wm * 32 + mi * 16 + a_row) * SROW + ks * 16 + a_ch]);
                LDSM4(a[mi][0], a[mi][1], a[mi][2], a[mi][3], addr);
            }
#pragma unroll
            for (int n2 = 0; n2 < 4; n2++) {
                uint32_t addr = smem_u32(&sB[cb][(wn * 64 + n2 * 16 + b_row) * SROW + ks * 16 + b_ch]);
                LDSM4(b[2 * n2][0], b[2 * n2][1], b[2 * n2 + 1][0], b[2 * n2 + 1][1], addr);
            }
#pragma unroll
            for (int mi = 0; mi < 2; mi++)
#pragma unroll
                for (int ni = 0; ni < 8; ni++)
                    MMA16(acc[mi][ni], a[mi], b[ni][0], b[ni][1]);
        }
    }

    float beta = 1.0f, omb = 0.0f;
    if (mode == 1) {
        float sv = *skipPtr;
        beta = 1.0f / (1.0f + expf(-sv));
        omb = 1.0f - beta;
    }

    const int rg = lane >> 2;
    const int cg = (lane & 3) * 2;
#pragma unroll
    for (int mi = 0; mi < 2; mi++) {
#pragma unroll
        for (int ni = 0; ni < 8; ni++) {
            int col = bn + wn * 64 + ni * 8 + cg;
            float2 bb = *(const float2*)(bias + col);
#pragma unroll
            for (int half = 0; half < 2; half++) {
                int row = bm + wm * 32 + mi * 16 + rg + half * 8;
                if (row >= Mtot) continue;
                float v0 = acc[mi][ni][half * 2 + 0] + bb.x;
                float v1 = acc[mi][ni][half * 2 + 1] + bb.y;
                if (mode == 1) {
                    float2 xo = __half22float2(
                        *(const __half2*)(xold16 + (size_t)row * DMC + col));
                    v0 = beta * v0 + omb * xo.x;
                    v1 = beta * v1 + omb * xo.y;
                }
                if (gelu_after) { v0 = gelu_f(v0); v1 = gelu_f(v1); }
                if (C)
                    *(float2*)(C + (size_t)row * ldc + col) = make_float2(v0, v1);
                if (C16) {
                    __half2 hv = __floats2half2_rn(v0, v1);
                    *(uint32_t*)(C16 + (size_t)row * ldc16 + col) = *(uint32_t*)&hv;
                }
            }
        }
    }
}

// ---------------------------------------------------------------------------
// Fused edge attention, one warp per dst, 4 heads in-warp (R12 body),
// dual-relation: first NPC warps handle P-dst, remaining NUC handle U-dst.
__device__ __forceinline__ float dot8(const uint4& ua, const float* qx) {
    float2 a0 = __half22float2(*(const __half2*)&ua.x);
    float2 a1 = __half22float2(*(const __half2*)&ua.y);
    float2 a2 = __half22float2(*(const __half2*)&ua.z);
    float2 a3 = __half22float2(*(const __half2*)&ua.w);
    float p = qx[0] * a0.x + qx[1] * a0.y;
    p = fmaf(qx[2], a1.x, p); p = fmaf(qx[3], a1.y, p);
    p = fmaf(qx[4], a2.x, p); p = fmaf(qx[5], a2.y, p);
    p = fmaf(qx[6], a3.x, p); p = fmaf(qx[7], a3.y, p);
    return p;
}

__global__ __launch_bounds__(256)
void agg_dual(const int* __restrict__ rowptrP, const int* __restrict__ colP,
              const __half* __restrict__ projP, const __half* __restrict__ projU,
              const float* __restrict__ prelP, const float* __restrict__ prelU,
              __half* __restrict__ agg16P, __half* __restrict__ agg16U) {
    int gid = blockIdx.x * blockDim.x + threadIdx.x;
    int w = gid >> 5;
    int lane = gid & 31;
    if (w >= NPC + NUC) return;
    const int sub = lane & 7;

    const int* rowptr;
    const int* col;
    const __half *q, *kt, *vt;
    const float* prel;
    __half* agg16;
    int dN;
    if (w < NPC) {
        dN = w;
        rowptr = rowptrP; col = colP;
        q = projP; kt = projU + DMC; vt = projU + 2 * DMC;
        prel = prelP; agg16 = agg16P;
    } else {
        dN = w - NPC;
        rowptr = rowptrP + (NPC + 1);          // rowptrU immediately follows
        col = colP + NEC;                       // colU immediately follows
        q = projU; kt = projP + DMC; vt = projP + 2 * DMC;
        prel = prelU; agg16 = agg16U;
    }

    int base = rowptr[dN];
    int deg = rowptr[dN + 1] - base;

    float acc[8] = {0.f, 0.f, 0.f, 0.f, 0.f, 0.f, 0.f, 0.f};
    if (deg > 0) {
        const size_t loff = (size_t)lane * 8;
        float qx[8];
        {
            uint4 uq = *(const uint4*)(q + (size_t)dN * LDPROJ + loff);
            float2 t0 = __half22float2(*(const __half2*)&uq.x);
            float2 t1 = __half22float2(*(const __half2*)&uq.y);
            float2 t2 = __half22float2(*(const __half2*)&uq.z);
            float2 t3 = __half22float2(*(const __half2*)&uq.w);
            qx[0] = t0.x; qx[1] = t0.y; qx[2] = t1.x; qx[3] = t1.y;
            qx[4] = t2.x; qx[5] = t2.y; qx[6] = t3.x; qx[7] = t3.y;
        }
        float pr = prel[lane >> 3] * 0.125f;

        if (deg <= 8) {
            float lg0 = -INFINITY;
            float m = -INFINITY;
            for (int j = 0; j < deg; j++) {
                int s = col[base + j];
                uint4 uk = *(const uint4*)(kt + (size_t)s * LDPROJ + loff);
                float p = dot8(uk, qx);
#pragma unroll
                for (int o = 4; o > 0; o >>= 1) p += __shfl_xor_sync(0xffffffffu, p, o);
                float lg = p * pr;
                if (j == sub) lg0 = lg;
                m = fmaxf(m, lg);
            }
            float e0 = (sub < deg) ? expf(lg0 - m) : 0.0f;
            float tsum = e0;
#pragma unroll
            for (int o = 4; o > 0; o >>= 1) tsum += __shfl_xor_sync(0xffffffffu, tsum, o);
            float inv = 1.0f / (tsum + 1e-16f);
            for (int j = 0; j < deg; j++) {
                float a = __shfl_sync(0xffffffffu, e0, (lane & 24) | j) * inv;
                int s = col[base + j];
                uint4 uv = *(const uint4*)(vt + (size_t)s * LDPROJ + loff);
                float2 v0 = __half22float2(*(const __half2*)&uv.x);
                float2 v1 = __half22float2(*(const __half2*)&uv.y);
                float2 v2 = __half22float2(*(const __half2*)&uv.z);
                float2 v3 = __half22float2(*(const __half2*)&uv.w);
                acc[0] = fmaf(a, v0.x, acc[0]); acc[1] = fmaf(a, v0.y, acc[1]);
                acc[2] = fmaf(a, v1.x, acc[2]); acc[3] = fmaf(a, v1.y, acc[3]);
                acc[4] = fmaf(a, v2.x, acc[4]); acc[5] = fmaf(a, v2.y, acc[5]);
                acc[6] = fmaf(a, v3.x, acc[6]); acc[7] = fmaf(a, v3.y, acc[7]);
            }
        } else {
            float m = -INFINITY;
            for (int j = 0; j < deg; j++) {
                int s = col[base + j];
                uint4 uk = *(const uint4*)(kt + (size_t)s * LDPROJ + loff);
                float p = dot8(uk, qx);
#pragma unroll
                for (int o = 4; o > 0; o >>= 1) p += __shfl_xor_sync(0xffffffffu, p, o);
                m = fmaxf(m, p * pr);
            }
            float ssum = 0.0f;
            for (int j = 0; j < deg; j++) {
                int s = col[base + j];
                uint4 uk = *(const uint4*)(kt + (size_t)s * LDPROJ + loff);
                float p = dot8(uk, qx);
#pragma unroll
                for (int o = 4; o > 0; o >>= 1) p += __shfl_xor_sync(0xffffffffu, p, o);
                ssum += expf(p * pr - m);
            }
            float inv = 1.0f / (ssum + 1e-16f);
            for (int j = 0; j < deg; j++) {
                int s = col[base + j];
                uint4 uk = *(const uint4*)(kt + (size_t)s * LDPROJ + loff);
                float p = dot8(uk, qx);
#pragma unroll
                for (int o = 4; o > 0; o >>= 1) p += __shfl_xor_sync(0xffffffffu, p, o);
                float a = expf(p * pr - m) * inv;
                uint4 uv = *(const uint4*)(vt + (size_t)s * LDPROJ + loff);
                float2 v0 = __half22float2(*(const __half2*)&uv.x);
                float2 v1 = __half22float2(*(const __half2*)&uv.y);
                float2 v2 = __half22float2(*(const __half2*)&uv.z);
                float2 v3 = __half22float2(*(const __half2*)&uv.w);
                acc[0] = fmaf(a, v0.x, acc[0]); acc[1] = fmaf(a, v0.y, acc[1]);
                acc[2] = fmaf(a, v1.x, acc[2]); acc[3] = fmaf(a, v1.y, acc[3]);
                acc[4] = fmaf(a, v2.x, acc[4]); acc[5] = fmaf(a, v2.y, acc[5]);
                acc[6] = fmaf(a, v3.x, acc[6]); acc[7] = fmaf(a, v3.y, acc[7]);
            }
        }
    }
    __half2 h0 = __floats2half2_rn(gelu_f(acc[0]), gelu_f(acc[1]));
    __half2 h1 = __floats2half2_rn(gelu_f(acc[2]), gelu_f(acc[3]));
    __half2 h2 = __floats2half2_rn(gelu_f(acc[4]), gelu_f(acc[5]));
    __half2 h3 = __floats2half2_rn(gelu_f(acc[6]), gelu_f(acc[7]));
    uint4 out = make_uint4(*(uint32_t*)&h0, *(uint32_t*)&h1, *(uint32_t*)&h2, *(uint32_t*)&h3);
    *(uint4*)(agg16 + (size_t)dN * DMC + (size_t)lane * 8) = out;
}

// ---------------------------------------------------------------------------
extern "C" void kernel_launch(void* const* d_in, const int* in_sizes, int n_in,
                              void* d_out, int out_size) {
    (void)in_sizes; (void)n_in; (void)out_size;

    float* base = nullptr;
    cudaGetSymbolAddress((void**)&base, g_buf);

    const int*   user_ids  = (const int*)d_in[0];
    const float* x_product = (const float*)d_in[1];
    const int*   edge_src  = (const int*)d_in[2];
    const int*   edge_dst  = (const int*)d_in[3];
    const float* emb       = (const float*)d_in[4];
    const float* Wk        = (const float*)d_in[5];
    const float* bk        = (const float*)d_in[6];
    const float* Wq        = (const float*)d_in[7];
    const float* bq        = (const float*)d_in[8];
    const float* Wv        = (const float*)d_in[9];
    const float* bv        = (const float*)d_in[10];
    const float* Wout      = (const float*)d_in[11];
    const float* bout      = (const float*)d_in[12];
    const float* skipp     = (const float*)d_in[13];
    const float* arel      = (const float*)d_in[14];
    const float* mrel      = (const float*)d_in[15];
    const float* prel      = (const float*)d_in[16];

    __half* WbigT   = (__half*)(base + OFF_WBIGT);
    float*  bbig    = base + OFF_BBIG;
    __half* WoutT   = (__half*)(base + OFF_WOUTT);
    __half* proj16U = (__half*)(base + H_PROJ16U);
    __half* proj16P = (__half*)(base + H_PROJ16P);
    __half* xu16A   = (__half*)(base + H_XU16A);
    __half* xu16B   = (__half*)(base + H_XU16B);
    __half* xp16A   = (__half*)(base + H_XP16A);
    __half* xp16B   = (__half*)(base + H_XP16B);
    __half* agg16U  = (__half*)(base + H_AGG16U);
    __half* agg16P  = (__half*)(base + H_AGG16P);

    int* ibase   = (int*)(base + OFF_INT);
    int* rowptrP = ibase + I_ROWP;
    int* rowptrU = ibase + I_ROWU;
    int* degP    = ibase + I_DEGP;
    int* degU    = ibase + I_DEGU;
    int* curP    = ibase + I_CURP;
    int* curU    = ibase + I_CURU;
    int* colP    = ibase + I_COLP;
    int* colU    = ibase + I_COLU;

    float* out_xu = (float*)d_out;
    float* out_xp = (float*)d_out + SZ_U;

    // 1. Weight assembly
    copyq_kernel<<<dim3(4, 256), 256>>>(Wq, bq, WbigT, bbig);
    fuse_w_kernel<<<dim3(8, 256), 256>>>(Wk, Wv, arel, mrel, WbigT);
    fuse_b_kernel<<<8, 256>>>(bk, bv, arel, mrel, bbig);
    woutT_kernel<<<dim3(4, 256), 256>>>(Wout, WoutT);

    // 2. Gather users (fp16); convert products (fp16)
    {
        size_t n = (size_t)NUC * (DMC / 4);
        gather_kernel<<<(unsigned)((n + 255) / 256), 256>>>(user_ids, emb, xu16A);
        size_t n4 = SZ_P / 4;
        conv16_kernel<<<(unsigned)((n4 + 255) / 256), 256>>>(x_product, xp16A, n4);
    }

    // 3. CSRs
    cudaMemsetAsync(degP, 0, (size_t)NPC * sizeof(int));
    cudaMemsetAsync(degU, 0, (size_t)NUC * sizeof(int));
    count_deg<<<(NEC + 255) / 256, 256>>>(edge_src, edge_dst, degP, degU);
    scan_kernel<<<1, 1024>>>(degP, rowptrP, curP, NPC);
    scan_kernel<<<1, 1024>>>(degU, rowptrU, curU, NUC);
    build_csr<<<(NEC + 255) / 256, 256>>>(edge_src, edge_dst, curP, curU, colP, colU);

    const unsigned gyU = (NUC + 127) / 128;
    const unsigned gyP = (NPC + 127) / 128;
    const unsigned aggBlocks = (unsigned)(((size_t)(NPC + NUC) * 32 + 255) / 256);

    for (int l = 0; l < 2; l++) {
        const __half* xu16_in = l ? xu16B : xu16A;
        const __half* xp16_in = l ? xp16B : xp16A;
        float* xu_out = l ? out_xu : nullptr;
        float* xp_out = l ? out_xp : nullptr;
        __half* xu16_out = l ? nullptr : xu16B;
        __half* xp16_out = l ? nullptr : xp16B;
        int gelu_after = (l == 0) ? 1 : 0;

        // Projections (fp16 outputs)
        {
            size_t cu = (size_t)(l * 2 + 0), cp = (size_t)(l * 2 + 1);
            gemm_fp16<<<dim3(LDPROJ / 128, gyU), 256>>>(
                xu16_in, WbigT + cu * LDPROJ * DMC, bbig + cu * LDPROJ,
                nullptr, 0, NUC, 0, nullptr, nullptr, 0, proj16U, LDPROJ);
            gemm_fp16<<<dim3(LDPROJ / 128, gyP), 256>>>(
                xp16_in, WbigT + cp * LDPROJ * DMC, bbig + cp * LDPROJ,
                nullptr, 0, NPC, 0, nullptr, nullptr, 0, proj16P, LDPROJ);
        }

        // Edge attention, both relations in one launch
        agg_dual<<<aggBlocks, 256>>>(rowptrP, colP, proj16P, proj16U,
                                     prel + (size_t)(l * 2 + 0) * NHC,
                                     prel + (size_t)(l * 2 + 1) * NHC,
                                     agg16P, agg16U);

        // Output GEMMs with fp16 skip blend (+ gelu for l==0)
        {
            gemm_fp16<<<dim3(DMC / 128, gyP), 256>>>(
                agg16P, WoutT + (size_t)(l * 2 + 1) * DMC * DMC, bout + (size_t)(l * 2 + 1) * DMC,
                xp_out, DMC, NPC, 1, xp16_in, skipp + (l * 2 + 1), gelu_after, xp16_out, DMC);
            gemm_fp16<<<dim3(DMC / 128, gyU), 256>>>(
                agg16U, WoutT + (size_t)(l * 2 + 0) * DMC * DMC, bout + (size_t)(l * 2 + 0) * DMC,
                xu_out, DMC, NUC, 1, xu16_in, skipp + (l * 2 + 0), gelu_after, xu16_out, DMC);
        }
    }
}

// round 15
// speedup vs baseline: 1.1837x; 1.0876x over previous
#include <cuda_runtime.h>
#include <cuda_fp16.h>
#include <math.h>
#include <stdint.h>

#define NUC 80000
#define NPC 40000
#define NEC 160000
#define DMC 256
#define NHC 4
#define NDC 64
#define LDPROJ 768

static const size_t SZ_U = (size_t)NUC * DMC;
static const size_t SZ_P = (size_t)NPC * DMC;

// Scratch layout (float units)
static const size_t OFF_WBIGT = 0;                              // fp16 [4][768][256]
static const size_t OFF_BBIG  = OFF_WBIGT + (size_t)4 * LDPROJ * DMC / 2;
static const size_t OFF_WOUTT = OFF_BBIG + 4 * LDPROJ;          // fp16 [4][256][256]
static const size_t OFF_INT   = OFF_WOUTT + (size_t)4 * DMC * DMC / 2;
static const size_t I_BASEP = 0;                 // base offsets (P dst)
static const size_t I_BASEU = I_BASEP + NPC;
static const size_t I_DEGP  = I_BASEU + NUC;
static const size_t I_DEGU  = I_DEGP + NPC;
static const size_t I_CURP  = I_DEGU + NUC;
static const size_t I_CURU  = I_CURP + NPC;
static const size_t I_COLP  = I_CURU + NUC;
static const size_t I_COLU  = I_COLP + NEC;
static const size_t I_CNT   = I_COLU + NEC;      // 2 counters
static const size_t N_INTS  = I_CNT + 2;
static const size_t OFF_H     = (OFF_INT + N_INTS + 3) & ~(size_t)3;
static const size_t H_PROJ16U = OFF_H;
static const size_t H_PROJ16P = H_PROJ16U + (size_t)NUC * LDPROJ / 2;
static const size_t H_XU16A   = H_PROJ16P + (size_t)NPC * LDPROJ / 2;
static const size_t H_XU16B   = H_XU16A + SZ_U / 2;
static const size_t H_XP16A   = H_XU16B + SZ_U / 2;
static const size_t H_XP16B   = H_XP16A + SZ_P / 2;
static const size_t H_AGG16U  = H_XP16B + SZ_P / 2;
static const size_t H_AGG16P  = H_AGG16U + SZ_U / 2;
static const size_t TOTAL_F   = H_AGG16P + SZ_P / 2;

__device__ float g_buf[TOTAL_F];

// ---------------------------------------------------------------------------
__device__ __forceinline__ float gelu_f(float x) {
    return 0.5f * x * (1.0f + erff(x * 0.70710678118654752f));
}
__device__ __forceinline__ uint32_t smem_u32(const void* p) {
    return (uint32_t)__cvta_generic_to_shared(p);
}

#define CP_ASYNC16(dst, src, sz) \
    asm volatile("cp.async.cg.shared.global [%0], [%1], 16, %2;" \
                 :: "r"(dst), "l"(src), "r"(sz) : "memory")
#define CP_COMMIT() asm volatile("cp.async.commit_group;" ::: "memory")
#define CP_WAIT0()  asm volatile("cp.async.wait_group 0;" ::: "memory")

#define LDSM4(r0, r1, r2, r3, addr) \
    asm volatile("ldmatrix.sync.aligned.m8n8.x4.shared.b16 {%0,%1,%2,%3}, [%4];" \
                 : "=r"(r0), "=r"(r1), "=r"(r2), "=r"(r3) : "r"(addr))

#define MMA16(d, av, b0v, b1v) \
    asm volatile("mma.sync.aligned.m16n8k16.row.col.f32.f16.f16.f32 " \
                 "{%0,%1,%2,%3}, {%4,%5,%6,%7}, {%8,%9}, {%0,%1,%2,%3};" \
                 : "+f"((d)[0]), "+f"((d)[1]), "+f"((d)[2]), "+f"((d)[3]) \
                 : "r"((av)[0]), "r"((av)[1]), "r"((av)[2]), "r"((av)[3]), \
                   "r"(b0v), "r"(b1v))

// ---------------------------------------------------------------------------
// Weight assembly (fp16, transposed [n][k])
__global__ void copyq_kernel(const float* __restrict__ Wq, const float* __restrict__ bq,
                             __half* __restrict__ WbigT, float* __restrict__ bbig) {
    int c = blockIdx.x, i = blockIdx.y, j = threadIdx.x;
    WbigT[((size_t)c * LDPROJ + j) * DMC + i] =
        __float2half_rn(Wq[(size_t)c * DMC * DMC + (size_t)i * DMC + j]);
    if (i == 0) bbig[(size_t)c * LDPROJ + j] = bq[(size_t)c * DMC + j];
}

__global__ void fuse_w_kernel(const float* __restrict__ Wk, const float* __restrict__ Wv,
                              const float* __restrict__ arel, const float* __restrict__ mrel,
                              __half* __restrict__ WbigT) {
    int c = blockIdx.x, i = blockIdx.y, j = threadIdx.x;
    int kv = c >> 2, lt = c & 3;
    const float* Wsrc = (kv ? Wv : Wk) + (size_t)lt * DMC * DMC;
    const float* R    = (kv ? mrel : arel) + (size_t)lt * NHC * NDC * NDC;
    int h = j >> 6, e = j & 63;
    const float* wrow = Wsrc + (size_t)i * DMC + h * NDC;
    const float* rr   = R + (size_t)h * NDC * NDC + e;
    float sum = 0.0f;
#pragma unroll 8
    for (int d = 0; d < NDC; d++) sum = fmaf(wrow[d], rr[(size_t)d * NDC], sum);
    int n = DMC + kv * DMC + j;
    WbigT[((size_t)lt * LDPROJ + n) * DMC + i] = __float2half_rn(sum);
}

__global__ void fuse_b_kernel(const float* __restrict__ bk, const float* __restrict__ bv,
                              const float* __restrict__ arel, const float* __restrict__ mrel,
                              float* __restrict__ bbig) {
    int c = blockIdx.x, j = threadIdx.x;
    int kv = c >> 2, lt = c & 3;
    const float* bsrc = (kv ? bv : bk) + (size_t)lt * DMC;
    const float* R    = (kv ? mrel : arel) + (size_t)lt * NHC * NDC * NDC;
    int h = j >> 6, e = j & 63;
    float sum = 0.0f;
#pragma unroll 8
    for (int d = 0; d < NDC; d++)
        sum = fmaf(bsrc[h * NDC + d], R[(size_t)h * NDC * NDC + (size_t)d * NDC + e], sum);
    bbig[(size_t)lt * LDPROJ + DMC + kv * DMC + j] = sum;
}

__global__ void woutT_kernel(const float* __restrict__ Wout, __half* __restrict__ WoutT) {
    int c = blockIdx.x, k = blockIdx.y, n = threadIdx.x;
    WoutT[((size_t)c * DMC + n) * DMC + k] =
        __float2half_rn(Wout[(size_t)c * DMC * DMC + (size_t)k * DMC + n]);
}

// ---------------------------------------------------------------------------
__global__ void gather_kernel(const int* __restrict__ ids, const float* __restrict__ tab,
                              __half* __restrict__ out16) {
    size_t i = (size_t)blockIdx.x * blockDim.x + threadIdx.x;
    if (i >= (size_t)NUC * (DMC / 4)) return;
    size_t row = i >> 6;
    int c4 = (int)(i & 63);
    float4 v = ((const float4*)(tab + (size_t)ids[row] * DMC))[c4];
    __half2 h0 = __floats2half2_rn(v.x, v.y);
    __half2 h1 = __floats2half2_rn(v.z, v.w);
    ((uint2*)out16)[i] = make_uint2(*(uint32_t*)&h0, *(uint32_t*)&h1);
}

__global__ void conv16_kernel(const float* __restrict__ src, __half* __restrict__ dst, size_t n4) {
    size_t i = (size_t)blockIdx.x * blockDim.x + threadIdx.x;
    if (i >= n4) return;
    float4 v = ((const float4*)src)[i];
    __half2 h0 = __floats2half2_rn(v.x, v.y);
    __half2 h1 = __floats2half2_rn(v.z, v.w);
    ((uint2*)dst)[i] = make_uint2(*(uint32_t*)&h0, *(uint32_t*)&h1);
}

// ---------------------------------------------------------------------------
// CSR construction (segment order nondeterministic; segments disjoint & exact)
__global__ void count_deg(const int* __restrict__ src, const int* __restrict__ dst,
                          int* __restrict__ degP, int* __restrict__ degU) {
    int e = blockIdx.x * blockDim.x + threadIdx.x;
    if (e >= NEC) return;
    atomicAdd(&degP[dst[e]], 1);
    atomicAdd(&degU[src[e]], 1);
}

// Multi-block atomic-offset scan: base[i] = block-local exclusive prefix +
// atomically-claimed block window. Writes base and cursor copies.
__global__ __launch_bounds__(256)
void base_kernel(const int* __restrict__ deg, int* __restrict__ basearr,
                 int* __restrict__ cursor, int n, int* __restrict__ gcount) {
    __shared__ int wsum[8];
    __shared__ int blockoff;
    int i = blockIdx.x * 256 + threadIdx.x;
    int lane = threadIdx.x & 31, wid = threadIdx.x >> 5;
    int d = (i < n) ? deg[i] : 0;
    int p = d;
#pragma unroll
    for (int o = 1; o < 32; o <<= 1) {
        int u = __shfl_up_sync(0xffffffffu, p, o);
        if (lane >= o) p += u;
    }
    if (lane == 31) wsum[wid] = p;
    __syncthreads();
    if (threadIdx.x == 0) {
        int s = 0;
#pragma unroll
        for (int w = 0; w < 8; w++) { int t = wsum[w]; wsum[w] = s; s += t; }
        blockoff = atomicAdd(gcount, s);
    }
    __syncthreads();
    if (i < n) {
        int excl = blockoff + wsum[wid] + p - d;
        basearr[i] = excl;
        cursor[i] = excl;
    }
}

__global__ void build_csr(const int* __restrict__ src, const int* __restrict__ dst,
                          int* __restrict__ curP, int* __restrict__ curU,
                          int* __restrict__ colP, int* __restrict__ colU) {
    int e = blockIdx.x * blockDim.x + threadIdx.x;
    if (e >= NEC) return;
    int s = src[e], d = dst[e];
    colP[atomicAdd(&curP[d], 1)] = s;
    colU[atomicAdd(&curU[s], 1)] = d;
}

// ---------------------------------------------------------------------------
// FP16 GEMM, cp.async double-buffer + ldmatrix + m16n8k16 (unchanged)
#define SROW 40
__global__ __launch_bounds__(256, 2)
void gemm_fp16(const __half* __restrict__ A16, const __half* __restrict__ BT,
               const float* __restrict__ bias, float* __restrict__ C, int ldc, int Mtot,
               int mode, const __half* __restrict__ xold16, const float* __restrict__ skipPtr,
               int gelu_after, __half* __restrict__ C16, int ldc16) {
    __shared__ __half sA[2][128 * SROW];
    __shared__ __half sB[2][128 * SROW];

    const int t = threadIdx.x;
    const int lane = t & 31;
    const int warp = t >> 5;
    const int wm = warp & 3;
    const int wn = warp >> 2;
    const int bm = blockIdx.y * 128;
    const int bn = blockIdx.x * 128;

    const int lr_ = t >> 2, lc_ = t & 3;
    const __half* gA0 = A16 + (size_t)(bm + lr_) * DMC + lc_ * 8;
    const __half* gA1 = A16 + (size_t)(bm + lr_ + 64) * DMC + lc_ * 8;
    const __half* gB0 = BT + (size_t)(bn + lr_) * DMC + lc_ * 8;
    const __half* gB1 = BT + (size_t)(bn + lr_ + 64) * DMC + lc_ * 8;
    const uint32_t szA0 = (bm + lr_ < Mtot) ? 16u : 0u;
    const uint32_t szA1 = (bm + lr_ + 64 < Mtot) ? 16u : 0u;
    uint32_t dA0[2], dA1[2], dB0[2], dB1[2];
#pragma unroll
    for (int b = 0; b < 2; b++) {
        dA0[b] = smem_u32(&sA[b][lr_ * SROW + lc_ * 8]);
        dA1[b] = smem_u32(&sA[b][(lr_ + 64) * SROW + lc_ * 8]);
        dB0[b] = smem_u32(&sB[b][lr_ * SROW + lc_ * 8]);
        dB1[b] = smem_u32(&sB[b][(lr_ + 64) * SROW + lc_ * 8]);
    }

    const int a_row = (lane & 7) + ((lane >> 3) & 1) * 8;
    const int a_ch  = ((lane >> 4) & 1) * 8;
    const int b_row = (lane & 7) + ((lane >> 4) & 1) * 8;
    const int b_ch  = ((lane >> 3) & 1) * 8;

    float acc[2][8][4];
#pragma unroll
    for (int mi = 0; mi < 2; mi++)
#pragma unroll
        for (int ni = 0; ni < 8; ni++)
#pragma unroll
            for (int r = 0; r < 4; r++) acc[mi][ni][r] = 0.0f;

    CP_ASYNC16(dA0[0], gA0, szA0);
    CP_ASYNC16(dA1[0], gA1, szA1);
    CP_ASYNC16(dB0[0], gB0, 16u);
    CP_ASYNC16(dB1[0], gB1, 16u);
    CP_COMMIT();

    for (int i = 0; i < 8; i++) {
        CP_WAIT0();
        __syncthreads();
        if (i < 7) {
            const int kn = (i + 1) * 32;
            const int nb = (i + 1) & 1;
            CP_ASYNC16(dA0[nb], gA0 + kn, szA0);
            CP_ASYNC16(dA1[nb], gA1 + kn, szA1);
            CP_ASYNC16(dB0[nb], gB0 + kn, 16u);
            CP_ASYNC16(dB1[nb], gB1 + kn, 16u);
            CP_COMMIT();
        }
        const int cb = i & 1;
#pragma unroll
        for (int ks = 0; ks < 2; ks++) {
            uint32_t a[2][4], b[8][2];
#pragma unroll
            for (int mi = 0; mi < 2; mi++) {
                uint32_t addr = smem_u32(&sA[cb][(wm * 32 + mi * 16 + a_row) * SROW + ks * 16 + a_ch]);
                LDSM4(a[mi][0], a[mi][1], a[mi][2], a[mi][3], addr);
            }
#pragma unroll
            for (int n2 = 0; n2 < 4; n2++) {
                uint32_t addr = smem_u32(&sB[cb][(wn * 64 + n2 * 16 + b_row) * SROW + ks * 16 + b_ch]);
                LDSM4(b[2 * n2][0], b[2 * n2][1], b[2 * n2 + 1][0], b[2 * n2 + 1][1], addr);
            }
#pragma unroll
            for (int mi = 0; mi < 2; mi++)
#pragma unroll
                for (int ni = 0; ni < 8; ni++)
                    MMA16(acc[mi][ni], a[mi], b[ni][0], b[ni][1]);
        }
    }

    float beta = 1.0f, omb = 0.0f;
    if (mode == 1) {
        float sv = *skipPtr;
        beta = 1.0f / (1.0f + expf(-sv));
        omb = 1.0f - beta;
    }

    const int rg = lane >> 2;
    const int cg = (lane & 3) * 2;
#pragma unroll
    for (int mi = 0; mi < 2; mi++) {
#pragma unroll
        for (int ni = 0; ni < 8; ni++) {
            int col = bn + wn * 64 + ni * 8 + cg;
            float2 bb = *(const float2*)(bias + col);
#pragma unroll
            for (int half = 0; half < 2; half++) {
                int row = bm + wm * 32 + mi * 16 + rg + half * 8;
                if (row >= Mtot) continue;
                float v0 = acc[mi][ni][half * 2 + 0] + bb.x;
                float v1 = acc[mi][ni][half * 2 + 1] + bb.y;
                if (mode == 1) {
                    float2 xo = __half22float2(
                        *(const __half2*)(xold16 + (size_t)row * DMC + col));
                    v0 = beta * v0 + omb * xo.x;
                    v1 = beta * v1 + omb * xo.y;
                }
                if (gelu_after) { v0 = gelu_f(v0); v1 = gelu_f(v1); }
                if (C)
                    *(float2*)(C + (size_t)row * ldc + col) = make_float2(v0, v1);
                if (C16) {
                    __half2 hv = __floats2half2_rn(v0, v1);
                    *(uint32_t*)(C16 + (size_t)row * ldc16 + col) = *(uint32_t*)&hv;
                }
            }
        }
    }
}

// ---------------------------------------------------------------------------
// Fused edge attention, one warp per dst, 4 heads in-warp, dual-relation.
__device__ __forceinline__ float dot8(const uint4& ua, const float* qx) {
    float2 a0 = __half22float2(*(const __half2*)&ua.x);
    float2 a1 = __half22float2(*(const __half2*)&ua.y);
    float2 a2 = __half22float2(*(const __half2*)&ua.z);
    float2 a3 = __half22float2(*(const __half2*)&ua.w);
    float p = qx[0] * a0.x + qx[1] * a0.y;
    p = fmaf(qx[2], a1.x, p); p = fmaf(qx[3], a1.y, p);
    p = fmaf(qx[4], a2.x, p); p = fmaf(qx[5], a2.y, p);
    p = fmaf(qx[6], a3.x, p); p = fmaf(qx[7], a3.y, p);
    return p;
}

__global__ __launch_bounds__(256)
void agg_dual(const int* __restrict__ baseP, const int* __restrict__ degPa,
              const int* __restrict__ colP,
              const __half* __restrict__ projP, const __half* __restrict__ projU,
              const float* __restrict__ prelP, const float* __restrict__ prelU,
              __half* __restrict__ agg16P, __half* __restrict__ agg16U) {
    int gid = blockIdx.x * blockDim.x + threadIdx.x;
    int w = gid >> 5;
    int lane = gid & 31;
    if (w >= NPC + NUC) return;
    const int sub = lane & 7;

    const int* col;
    const __half *q, *kt, *vt;
    const float* prel;
    __half* agg16;
    int dN, base, deg;
    if (w < NPC) {
        dN = w;
        base = baseP[dN];
        deg  = degPa[dN];
        col = colP;
        q = projP; kt = projU + DMC; vt = projU + 2 * DMC;
        prel = prelP; agg16 = agg16P;
    } else {
        dN = w - NPC;
        base = baseP[NPC + dN];        // baseU follows baseP
        deg  = degPa[NPC + dN];        // degU follows degP
        col = colP + NEC;              // colU follows colP
        q = projU; kt = projP + DMC; vt = projP + 2 * DMC;
        prel = prelU; agg16 = agg16U;
    }

    float acc[8] = {0.f, 0.f, 0.f, 0.f, 0.f, 0.f, 0.f, 0.f};
    if (deg > 0) {
        const size_t loff = (size_t)lane * 8;
        float qx[8];
        {
            uint4 uq = *(const uint4*)(q + (size_t)dN * LDPROJ + loff);
            float2 t0 = __half22float2(*(const __half2*)&uq.x);
            float2 t1 = __half22float2(*(const __half2*)&uq.y);
            float2 t2 = __half22float2(*(const __half2*)&uq.z);
            float2 t3 = __half22float2(*(const __half2*)&uq.w);
            qx[0] = t0.x; qx[1] = t0.y; qx[2] = t1.x; qx[3] = t1.y;
            qx[4] = t2.x; qx[5] = t2.y; qx[6] = t3.x; qx[7] = t3.y;
        }
        float pr = prel[lane >> 3] * 0.125f;

        if (deg <= 8) {
            float lg0 = -INFINITY;
            float m = -INFINITY;
            for (int j = 0; j < deg; j++) {
                int s = col[base + j];
                uint4 uk = *(const uint4*)(kt + (size_t)s * LDPROJ + loff);
                float p = dot8(uk, qx);
#pragma unroll
                for (int o = 4; o > 0; o >>= 1) p += __shfl_xor_sync(0xffffffffu, p, o);
                float lg = p * pr;
                if (j == sub) lg0 = lg;
                m = fmaxf(m, lg);
            }
            float e0 = (sub < deg) ? expf(lg0 - m) : 0.0f;
            float tsum = e0;
#pragma unroll
            for (int o = 4; o > 0; o >>= 1) tsum += __shfl_xor_sync(0xffffffffu, tsum, o);
            float inv = 1.0f / (tsum + 1e-16f);
            for (int j = 0; j < deg; j++) {
                float a = __shfl_sync(0xffffffffu, e0, (lane & 24) | j) * inv;
                int s = col[base + j];
                uint4 uv = *(const uint4*)(vt + (size_t)s * LDPROJ + loff);
                float2 v0 = __half22float2(*(const __half2*)&uv.x);
                float2 v1 = __half22float2(*(const __half2*)&uv.y);
                float2 v2 = __half22float2(*(const __half2*)&uv.z);
                float2 v3 = __half22float2(*(const __half2*)&uv.w);
                acc[0] = fmaf(a, v0.x, acc[0]); acc[1] = fmaf(a, v0.y, acc[1]);
                acc[2] = fmaf(a, v1.x, acc[2]); acc[3] = fmaf(a, v1.y, acc[3]);
                acc[4] = fmaf(a, v2.x, acc[4]); acc[5] = fmaf(a, v2.y, acc[5]);
                acc[6] = fmaf(a, v3.x, acc[6]); acc[7] = fmaf(a, v3.y, acc[7]);
            }
        } else {
            float m = -INFINITY;
            for (int j = 0; j < deg; j++) {
                int s = col[base + j];
                uint4 uk = *(const uint4*)(kt + (size_t)s * LDPROJ + loff);
                float p = dot8(uk, qx);
#pragma unroll
                for (int o = 4; o > 0; o >>= 1) p += __shfl_xor_sync(0xffffffffu, p, o);
                m = fmaxf(m, p * pr);
            }
            float ssum = 0.0f;
            for (int j = 0; j < deg; j++) {
                int s = col[base + j];
                uint4 uk = *(const uint4*)(kt + (size_t)s * LDPROJ + loff);
                float p = dot8(uk, qx);
#pragma unroll
                for (int o = 4; o > 0; o >>= 1) p += __shfl_xor_sync(0xffffffffu, p, o);
                ssum += expf(p * pr - m);
            }
            float inv = 1.0f / (ssum + 1e-16f);
            for (int j = 0; j < deg; j++) {
                int s = col[base + j];
                uint4 uk = *(const uint4*)(kt + (size_t)s * LDPROJ + loff);
                float p = dot8(uk, qx);
#pragma unroll
                for (int o = 4; o > 0; o >>= 1) p += __shfl_xor_sync(0xffffffffu, p, o);
                float a = expf(p * pr - m) * inv;
                uint4 uv = *(const uint4*)(vt + (size_t)s * LDPROJ + loff);
                float2 v0 = __half22float2(*(const __half2*)&uv.x);
                float2 v1 = __half22float2(*(const __half2*)&uv.y);
                float2 v2 = __half22float2(*(const __half2*)&uv.z);
                float2 v3 = __half22float2(*(const __half2*)&uv.w);
                acc[0] = fmaf(a, v0.x, acc[0]); acc[1] = fmaf(a, v0.y, acc[1]);
                acc[2] = fmaf(a, v1.x, acc[2]); acc[3] = fmaf(a, v1.y, acc[3]);
                acc[4] = fmaf(a, v2.x, acc[4]); acc[5] = fmaf(a, v2.y, acc[5]);
                acc[6] = fmaf(a, v3.x, acc[6]); acc[7] = fmaf(a, v3.y, acc[7]);
            }
        }
    }
    __half2 h0 = __floats2half2_rn(gelu_f(acc[0]), gelu_f(acc[1]));
    __half2 h1 = __floats2half2_rn(gelu_f(acc[2]), gelu_f(acc[3]));
    __half2 h2 = __floats2half2_rn(gelu_f(acc[4]), gelu_f(acc[5]));
    __half2 h3 = __floats2half2_rn(gelu_f(acc[6]), gelu_f(acc[7]));
    uint4 out = make_uint4(*(uint32_t*)&h0, *(uint32_t*)&h1, *(uint32_t*)&h2, *(uint32_t*)&h3);
    *(uint4*)(agg16 + (size_t)dN * DMC + (size_t)lane * 8) = out;
}

// ---------------------------------------------------------------------------
extern "C" void kernel_launch(void* const* d_in, const int* in_sizes, int n_in,
                              void* d_out, int out_size) {
    (void)in_sizes; (void)n_in; (void)out_size;

    float* base = nullptr;
    cudaGetSymbolAddress((void**)&base, g_buf);

    const int*   user_ids  = (const int*)d_in[0];
    const float* x_product = (const float*)d_in[1];
    const int*   edge_src  = (const int*)d_in[2];
    const int*   edge_dst  = (const int*)d_in[3];
    const float* emb       = (const float*)d_in[4];
    const float* Wk        = (const float*)d_in[5];
    const float* bk        = (const float*)d_in[6];
    const float* Wq        = (const float*)d_in[7];
    const float* bq        = (const float*)d_in[8];
    const float* Wv        = (const float*)d_in[9];
    const float* bv        = (const float*)d_in[10];
    const float* Wout      = (const float*)d_in[11];
    const float* bout      = (const float*)d_in[12];
    const float* skipp     = (const float*)d_in[13];
    const float* arel      = (const float*)d_in[14];
    const float* mrel      = (const float*)d_in[15];
    const float* prel      = (const float*)d_in[16];

    __half* WbigT   = (__half*)(base + OFF_WBIGT);
    float*  bbig    = base + OFF_BBIG;
    __half* WoutT   = (__half*)(base + OFF_WOUTT);
    __half* proj16U = (__half*)(base + H_PROJ16U);
    __half* proj16P = (__half*)(base + H_PROJ16P);
    __half* xu16A   = (__half*)(base + H_XU16A);
    __half* xu16B   = (__half*)(base + H_XU16B);
    __half* xp16A   = (__half*)(base + H_XP16A);
    __half* xp16B   = (__half*)(base + H_XP16B);
    __half* agg16U  = (__half*)(base + H_AGG16U);
    __half* agg16P  = (__half*)(base + H_AGG16P);

    int* ibase = (int*)(base + OFF_INT);
    int* baseP = ibase + I_BASEP;
    int* baseU = ibase + I_BASEU;
    int* degP  = ibase + I_DEGP;
    int* degU  = ibase + I_DEGU;
    int* curP  = ibase + I_CURP;
    int* curU  = ibase + I_CURU;
    int* colP  = ibase + I_COLP;
    int* colU  = ibase + I_COLU;
    int* cnt   = ibase + I_CNT;

    float* out_xu = (float*)d_out;
    float* out_xp = (float*)d_out + SZ_U;

    // 1. Weight assembly
    copyq_kernel<<<dim3(4, 256), 256>>>(Wq, bq, WbigT, bbig);
    fuse_w_kernel<<<dim3(8, 256), 256>>>(Wk, Wv, arel, mrel, WbigT);
    fuse_b_kernel<<<8, 256>>>(bk, bv, arel, mrel, bbig);
    woutT_kernel<<<dim3(4, 256), 256>>>(Wout, WoutT);

    // 2. Gather users (fp16); convert products (fp16)
    {
        size_t n = (size_t)NUC * (DMC / 4);
        gather_kernel<<<(unsigned)((n + 255) / 256), 256>>>(user_ids, emb, xu16A);
        size_t n4 = SZ_P / 4;
        conv16_kernel<<<(unsigned)((n4 + 255) / 256), 256>>>(x_product, xp16A, n4);
    }

    // 3. Segment tables (multi-block atomic-offset scan; order nondeterministic)
    cudaMemsetAsync(degP, 0, (size_t)(NPC + NUC) * sizeof(int));   // degP + degU
    cudaMemsetAsync(cnt, 0, 2 * sizeof(int));
    count_deg<<<(NEC + 255) / 256, 256>>>(edge_src, edge_dst, degP, degU);
    base_kernel<<<(NPC + 255) / 256, 256>>>(degP, baseP, curP, NPC, cnt + 0);
    base_kernel<<<(NUC + 255) / 256, 256>>>(degU, baseU, curU, NUC, cnt + 1);
    build_csr<<<(NEC + 255) / 256, 256>>>(edge_src, edge_dst, curP, curU, colP, colU);

    const unsigned gyU = (NUC + 127) / 128;
    const unsigned gyP = (NPC + 127) / 128;
    const unsigned aggBlocks = (unsigned)(((size_t)(NPC + NUC) * 32 + 255) / 256);

    for (int l = 0; l < 2; l++) {
        const __half* xu16_in = l ? xu16B : xu16A;
        const __half* xp16_in = l ? xp16B : xp16A;
        float* xu_out = l ? out_xu : nullptr;
        float* xp_out = l ? out_xp : nullptr;
        __half* xu16_out = l ? nullptr : xu16B;
        __half* xp16_out = l ? nullptr : xp16B;
        int gelu_after = (l == 0) ? 1 : 0;

        // Projections (fp16 outputs)
        {
            size_t cu = (size_t)(l * 2 + 0), cp = (size_t)(l * 2 + 1);
            gemm_fp16<<<dim3(LDPROJ / 128, gyU), 256>>>(
                xu16_in, WbigT + cu * LDPROJ * DMC, bbig + cu * LDPROJ,
                nullptr, 0, NUC, 0, nullptr, nullptr, 0, proj16U, LDPROJ);
            gemm_fp16<<<dim3(LDPROJ / 128, gyP), 256>>>(
                xp16_in, WbigT + cp * LDPROJ * DMC, bbig + cp * LDPROJ,
                nullptr, 0, NPC, 0, nullptr, nullptr, 0, proj16P, LDPROJ);
        }

        // Edge attention, both relations in one launch
        agg_dual<<<aggBlocks, 256>>>(baseP, degP, colP, proj16P, proj16U,
                                     prel + (size_t)(l * 2 + 0) * NHC,
                                     prel + (size_t)(l * 2 + 1) * NHC,
                                     agg16P, agg16U);

        // Output GEMMs with fp16 skip blend (+ gelu for l==0)
        {
            gemm_fp16<<<dim3(DMC / 128, gyP), 256>>>(
                agg16P, WoutT + (size_t)(l * 2 + 1) * DMC * DMC, bout + (size_t)(l * 2 + 1) * DMC,
                xp_out, DMC, NPC, 1, xp16_in, skipp + (l * 2 + 1), gelu_after, xp16_out, DMC);
            gemm_fp16<<<dim3(DMC / 128, gyU), 256>>>(
                agg16U, WoutT + (size_t)(l * 2 + 0) * DMC * DMC, bout + (size_t)(l * 2 + 0) * DMC,
                xu_out, DMC, NUC, 1, xu16_in, skipp + (l * 2 + 0), gelu_after, xu16_out, DMC);
        }
    }
}

// round 16
// speedup vs baseline: 1.2008x; 1.0145x over previous
#include <cuda_runtime.h>
#include <cuda_fp16.h>
#include <math.h>
#include <stdint.h>

#define NUC 80000
#define NPC 40000
#define NEC 160000
#define DMC 256
#define NHC 4
#define NDC 64
#define LDPROJ 768

static const size_t SZ_U = (size_t)NUC * DMC;
static const size_t SZ_P = (size_t)NPC * DMC;

// Scratch layout (float units)
static const size_t OFF_WBIGT = 0;                              // fp16 [4][768][256]
static const size_t OFF_BBIG  = OFF_WBIGT + (size_t)4 * LDPROJ * DMC / 2;
static const size_t OFF_WOUTT = OFF_BBIG + 4 * LDPROJ;          // fp16 [4][256][256]
static const size_t OFF_INT   = OFF_WOUTT + (size_t)4 * DMC * DMC / 2;
static const size_t I_BASEP = 0;
static const size_t I_BASEU = I_BASEP + NPC;
static const size_t I_DEGP  = I_BASEU + NUC;
static const size_t I_DEGU  = I_DEGP + NPC;
static const size_t I_CURP  = I_DEGU + NUC;
static const size_t I_CURU  = I_CURP + NPC;
static const size_t I_COLP  = I_CURU + NUC;
static const size_t I_COLU  = I_COLP + NEC;
static const size_t I_CNT   = I_COLU + NEC;
static const size_t N_INTS  = I_CNT + 2;
static const size_t OFF_H     = (OFF_INT + N_INTS + 3) & ~(size_t)3;
static const size_t H_PROJ16U = OFF_H;
static const size_t H_PROJ16P = H_PROJ16U + (size_t)NUC * LDPROJ / 2;
static const size_t H_XU16A   = H_PROJ16P + (size_t)NPC * LDPROJ / 2;
static const size_t H_XU16B   = H_XU16A + SZ_U / 2;
static const size_t H_XP16A   = H_XU16B + SZ_U / 2;
static const size_t H_XP16B   = H_XP16A + SZ_P / 2;
static const size_t H_AGG16U  = H_XP16B + SZ_P / 2;
static const size_t H_AGG16P  = H_AGG16U + SZ_U / 2;
static const size_t TOTAL_F   = H_AGG16P + SZ_P / 2;

__device__ float g_buf[TOTAL_F];

// ---------------------------------------------------------------------------
__device__ __forceinline__ float gelu_f(float x) {
    return 0.5f * x * (1.0f + erff(x * 0.70710678118654752f));
}
__device__ __forceinline__ uint32_t smem_u32(const void* p) {
    return (uint32_t)__cvta_generic_to_shared(p);
}

#define CP_ASYNC16(dst, src, sz) \
    asm volatile("cp.async.cg.shared.global [%0], [%1], 16, %2;" \
                 :: "r"(dst), "l"(src), "r"(sz) : "memory")
#define CP_COMMIT() asm volatile("cp.async.commit_group;" ::: "memory")
#define CP_WAIT0()  asm volatile("cp.async.wait_group 0;" ::: "memory")

#define LDSM4(r0, r1, r2, r3, addr) \
    asm volatile("ldmatrix.sync.aligned.m8n8.x4.shared.b16 {%0,%1,%2,%3}, [%4];" \
                 : "=r"(r0), "=r"(r1), "=r"(r2), "=r"(r3) : "r"(addr))

#define MMA16(d, av, b0v, b1v) \
    asm volatile("mma.sync.aligned.m16n8k16.row.col.f32.f16.f16.f32 " \
                 "{%0,%1,%2,%3}, {%4,%5,%6,%7}, {%8,%9}, {%0,%1,%2,%3};" \
                 : "+f"((d)[0]), "+f"((d)[1]), "+f"((d)[2]), "+f"((d)[3]) \
                 : "r"((av)[0]), "r"((av)[1]), "r"((av)[2]), "r"((av)[3]), \
                   "r"(b0v), "r"(b1v))

// ---------------------------------------------------------------------------
// Weight assembly (fp16, transposed [n][k])
__global__ void copyq_kernel(const float* __restrict__ Wq, const float* __restrict__ bq,
                             __half* __restrict__ WbigT, float* __restrict__ bbig) {
    int c = blockIdx.x, i = blockIdx.y, j = threadIdx.x;
    WbigT[((size_t)c * LDPROJ + j) * DMC + i] =
        __float2half_rn(Wq[(size_t)c * DMC * DMC + (size_t)i * DMC + j]);
    if (i == 0) bbig[(size_t)c * LDPROJ + j] = bq[(size_t)c * DMC + j];
}

__global__ void fuse_w_kernel(const float* __restrict__ Wk, const float* __restrict__ Wv,
                              const float* __restrict__ arel, const float* __restrict__ mrel,
                              __half* __restrict__ WbigT) {
    int c = blockIdx.x, i = blockIdx.y, j = threadIdx.x;
    int kv = c >> 2, lt = c & 3;
    const float* Wsrc = (kv ? Wv : Wk) + (size_t)lt * DMC * DMC;
    const float* R    = (kv ? mrel : arel) + (size_t)lt * NHC * NDC * NDC;
    int h = j >> 6, e = j & 63;
    const float* wrow = Wsrc + (size_t)i * DMC + h * NDC;
    const float* rr   = R + (size_t)h * NDC * NDC + e;
    float sum = 0.0f;
#pragma unroll 8
    for (int d = 0; d < NDC; d++) sum = fmaf(wrow[d], rr[(size_t)d * NDC], sum);
    int n = DMC + kv * DMC + j;
    WbigT[((size_t)lt * LDPROJ + n) * DMC + i] = __float2half_rn(sum);
}

__global__ void fuse_b_kernel(const float* __restrict__ bk, const float* __restrict__ bv,
                              const float* __restrict__ arel, const float* __restrict__ mrel,
                              float* __restrict__ bbig) {
    int c = blockIdx.x, j = threadIdx.x;
    int kv = c >> 2, lt = c & 3;
    const float* bsrc = (kv ? bv : bk) + (size_t)lt * DMC;
    const float* R    = (kv ? mrel : arel) + (size_t)lt * NHC * NDC * NDC;
    int h = j >> 6, e = j & 63;
    float sum = 0.0f;
#pragma unroll 8
    for (int d = 0; d < NDC; d++)
        sum = fmaf(bsrc[h * NDC + d], R[(size_t)h * NDC * NDC + (size_t)d * NDC + e], sum);
    bbig[(size_t)lt * LDPROJ + DMC + kv * DMC + j] = sum;
}

__global__ void woutT_kernel(const float* __restrict__ Wout, __half* __restrict__ WoutT) {
    int c = blockIdx.x, k = blockIdx.y, n = threadIdx.x;
    WoutT[((size_t)c * DMC + n) * DMC + k] =
        __float2half_rn(Wout[(size_t)c * DMC * DMC + (size_t)k * DMC + n]);
}

// ---------------------------------------------------------------------------
// Merged gather (users) + convert (products), fp16 outputs
__global__ void prep16_kernel(const int* __restrict__ ids, const float* __restrict__ tab,
                              const float* __restrict__ xprod,
                              __half* __restrict__ xu16, __half* __restrict__ xp16) {
    size_t i = (size_t)blockIdx.x * blockDim.x + threadIdx.x;
    const size_t nU = (size_t)NUC * (DMC / 4);
    const size_t nP = (size_t)NPC * (DMC / 4);
    if (i < nU) {
        size_t row = i >> 6;
        int c4 = (int)(i & 63);
        float4 v = ((const float4*)(tab + (size_t)ids[row] * DMC))[c4];
        __half2 h0 = __floats2half2_rn(v.x, v.y);
        __half2 h1 = __floats2half2_rn(v.z, v.w);
        ((uint2*)xu16)[i] = make_uint2(*(uint32_t*)&h0, *(uint32_t*)&h1);
    } else if (i < nU + nP) {
        size_t j = i - nU;
        float4 v = ((const float4*)xprod)[j];
        __half2 h0 = __floats2half2_rn(v.x, v.y);
        __half2 h1 = __floats2half2_rn(v.z, v.w);
        ((uint2*)xp16)[j] = make_uint2(*(uint32_t*)&h0, *(uint32_t*)&h1);
    }
}

// ---------------------------------------------------------------------------
// CSR construction (segment order nondeterministic; segments disjoint & exact)
__global__ void count_deg(const int* __restrict__ src, const int* __restrict__ dst,
                          int* __restrict__ degP, int* __restrict__ degU) {
    int e = blockIdx.x * blockDim.x + threadIdx.x;
    if (e >= NEC) return;
    atomicAdd(&degP[dst[e]], 1);
    atomicAdd(&degU[src[e]], 1);
}

__global__ __launch_bounds__(256)
void base_kernel(const int* __restrict__ deg, int* __restrict__ basearr,
                 int* __restrict__ cursor, int n, int* __restrict__ gcount) {
    __shared__ int wsum[8];
    __shared__ int blockoff;
    int i = blockIdx.x * 256 + threadIdx.x;
    int lane = threadIdx.x & 31, wid = threadIdx.x >> 5;
    int d = (i < n) ? deg[i] : 0;
    int p = d;
#pragma unroll
    for (int o = 1; o < 32; o <<= 1) {
        int u = __shfl_up_sync(0xffffffffu, p, o);
        if (lane >= o) p += u;
    }
    if (lane == 31) wsum[wid] = p;
    __syncthreads();
    if (threadIdx.x == 0) {
        int s = 0;
#pragma unroll
        for (int w = 0; w < 8; w++) { int t = wsum[w]; wsum[w] = s; s += t; }
        blockoff = atomicAdd(gcount, s);
    }
    __syncthreads();
    if (i < n) {
        int excl = blockoff + wsum[wid] + p - d;
        basearr[i] = excl;
        cursor[i] = excl;
    }
}

__global__ void build_csr(const int* __restrict__ src, const int* __restrict__ dst,
                          int* __restrict__ curP, int* __restrict__ curU,
                          int* __restrict__ colP, int* __restrict__ colU) {
    int e = blockIdx.x * blockDim.x + threadIdx.x;
    if (e >= NEC) return;
    int s = src[e], d = dst[e];
    colP[atomicAdd(&curP[d], 1)] = s;
    colU[atomicAdd(&curU[s], 1)] = d;
}

// ---------------------------------------------------------------------------
// FP16 GEMM, DUAL (U + P in one launch, selected by blockIdx.y).
// Inner loop identical to R15's gemm_fp16.
#define SROW 40
__global__ __launch_bounds__(256, 2)
void gemm_dual(const __half* __restrict__ Au, const __half* __restrict__ Bu,
               const float* __restrict__ biasu, float* __restrict__ Cu,
               __half* __restrict__ C16u, const __half* __restrict__ xoldu,
               const float* __restrict__ skipu,
               const __half* __restrict__ Ap, const __half* __restrict__ Bp,
               const float* __restrict__ biasp, float* __restrict__ Cp,
               __half* __restrict__ C16p, const __half* __restrict__ xoldp,
               const float* __restrict__ skipp_,
               int gyU, int ldc, int ldc16, int mode, int gelu_after) {
    __shared__ __half sA[2][128 * SROW];
    __shared__ __half sB[2][128 * SROW];

    const __half *A16, *BT;
    const float* bias;
    float* C;
    __half* C16;
    const __half* xold16;
    const float* skipPtr;
    int Mtot, bm;
    if ((int)blockIdx.y < gyU) {
        A16 = Au; BT = Bu; bias = biasu; C = Cu; C16 = C16u;
        xold16 = xoldu; skipPtr = skipu;
        Mtot = NUC; bm = blockIdx.y * 128;
    } else {
        A16 = Ap; BT = Bp; bias = biasp; C = Cp; C16 = C16p;
        xold16 = xoldp; skipPtr = skipp_;
        Mtot = NPC; bm = (blockIdx.y - gyU) * 128;
    }

    const int t = threadIdx.x;
    const int lane = t & 31;
    const int warp = t >> 5;
    const int wm = warp & 3;
    const int wn = warp >> 2;
    const int bn = blockIdx.x * 128;

    const int lr_ = t >> 2, lc_ = t & 3;
    const __half* gA0 = A16 + (size_t)(bm + lr_) * DMC + lc_ * 8;
    const __half* gA1 = A16 + (size_t)(bm + lr_ + 64) * DMC + lc_ * 8;
    const __half* gB0 = BT + (size_t)(bn + lr_) * DMC + lc_ * 8;
    const __half* gB1 = BT + (size_t)(bn + lr_ + 64) * DMC + lc_ * 8;
    const uint32_t szA0 = (bm + lr_ < Mtot) ? 16u : 0u;
    const uint32_t szA1 = (bm + lr_ + 64 < Mtot) ? 16u : 0u;
    uint32_t dA0[2], dA1[2], dB0[2], dB1[2];
#pragma unroll
    for (int b = 0; b < 2; b++) {
        dA0[b] = smem_u32(&sA[b][lr_ * SROW + lc_ * 8]);
        dA1[b] = smem_u32(&sA[b][(lr_ + 64) * SROW + lc_ * 8]);
        dB0[b] = smem_u32(&sB[b][lr_ * SROW + lc_ * 8]);
        dB1[b] = smem_u32(&sB[b][(lr_ + 64) * SROW + lc_ * 8]);
    }

    const int a_row = (lane & 7) + ((lane >> 3) & 1) * 8;
    const int a_ch  = ((lane >> 4) & 1) * 8;
    const int b_row = (lane & 7) + ((lane >> 4) & 1) * 8;
    const int b_ch  = ((lane >> 3) & 1) * 8;

    float acc[2][8][4];
#pragma unroll
    for (int mi = 0; mi < 2; mi++)
#pragma unroll
        for (int ni = 0; ni < 8; ni++)
#pragma unroll
            for (int r = 0; r < 4; r++) acc[mi][ni][r] = 0.0f;

    CP_ASYNC16(dA0[0], gA0, szA0);
    CP_ASYNC16(dA1[0], gA1, szA1);
    CP_ASYNC16(dB0[0], gB0, 16u);
    CP_ASYNC16(dB1[0], gB1, 16u);
    CP_COMMIT();

    for (int i = 0; i < 8; i++) {
        CP_WAIT0();
        __syncthreads();
        if (i < 7) {
            const int kn = (i + 1) * 32;
            const int nb = (i + 1) & 1;
            CP_ASYNC16(dA0[nb], gA0 + kn, szA0);
            CP_ASYNC16(dA1[nb], gA1 + kn, szA1);
            CP_ASYNC16(dB0[nb], gB0 + kn, 16u);
            CP_ASYNC16(dB1[nb], gB1 + kn, 16u);
            CP_COMMIT();
        }
        const int cb = i & 1;
#pragma unroll
        for (int ks = 0; ks < 2; ks++) {
            uint32_t a[2][4], b[8][2];
#pragma unroll
            for (int mi = 0; mi < 2; mi++) {
                uint32_t addr = smem_u32(&sA[cb][(wm * 32 + mi * 16 + a_row) * SROW + ks * 16 + a_ch]);
                LDSM4(a[mi][0], a[mi][1], a[mi][2], a[mi][3], addr);
            }
#pragma unroll
            for (int n2 = 0; n2 < 4; n2++) {
                uint32_t addr = smem_u32(&sB[cb][(wn * 64 + n2 * 16 + b_row) * SROW + ks * 16 + b_ch]);
                LDSM4(b[2 * n2][0], b[2 * n2][1], b[2 * n2 + 1][0], b[2 * n2 + 1][1], addr);
            }
#pragma unroll
            for (int mi = 0; mi < 2; mi++)
#pragma unroll
                for (int ni = 0; ni < 8; ni++)
                    MMA16(acc[mi][ni], a[mi], b[ni][0], b[ni][1]);
        }
    }

    float beta = 1.0f, omb = 0.0f;
    if (mode == 1) {
        float sv = *skipPtr;
        beta = 1.0f / (1.0f + expf(-sv));
        omb = 1.0f - beta;
    }

    const int rg = lane >> 2;
    const int cg = (lane & 3) * 2;
#pragma unroll
    for (int mi = 0; mi < 2; mi++) {
#pragma unroll
        for (int ni = 0; ni < 8; ni++) {
            int col = bn + wn * 64 + ni * 8 + cg;
            float2 bb = *(const float2*)(bias + col);
#pragma unroll
            for (int half = 0; half < 2; half++) {
                int row = bm + wm * 32 + mi * 16 + rg + half * 8;
                if (row >= Mtot) continue;
                float v0 = acc[mi][ni][half * 2 + 0] + bb.x;
                float v1 = acc[mi][ni][half * 2 + 1] + bb.y;
                if (mode == 1) {
                    float2 xo = __half22float2(
                        *(const __half2*)(xold16 + (size_t)row * DMC + col));
                    v0 = beta * v0 + omb * xo.x;
                    v1 = beta * v1 + omb * xo.y;
                }
                if (gelu_after) { v0 = gelu_f(v0); v1 = gelu_f(v1); }
                if (C)
                    *(float2*)(C + (size_t)row * ldc + col) = make_float2(v0, v1);
                if (C16) {
                    __half2 hv = __floats2half2_rn(v0, v1);
                    *(uint32_t*)(C16 + (size_t)row * ldc16 + col) = *(uint32_t*)&hv;
                }
            }
        }
    }
}

// ---------------------------------------------------------------------------
// Fused edge attention, one warp per dst, 4 heads in-warp, dual-relation (R15).
__device__ __forceinline__ float dot8(const uint4& ua, const float* qx) {
    float2 a0 = __half22float2(*(const __half2*)&ua.x);
    float2 a1 = __half22float2(*(const __half2*)&ua.y);
    float2 a2 = __half22float2(*(const __half2*)&ua.z);
    float2 a3 = __half22float2(*(const __half2*)&ua.w);
    float p = qx[0] * a0.x + qx[1] * a0.y;
    p = fmaf(qx[2], a1.x, p); p = fmaf(qx[3], a1.y, p);
    p = fmaf(qx[4], a2.x, p); p = fmaf(qx[5], a2.y, p);
    p = fmaf(qx[6], a3.x, p); p = fmaf(qx[7], a3.y, p);
    return p;
}

__global__ __launch_bounds__(256)
void agg_dual(const int* __restrict__ baseP, const int* __restrict__ degPa,
              const int* __restrict__ colP,
              const __half* __restrict__ projP, const __half* __restrict__ projU,
              const float* __restrict__ prelP, const float* __restrict__ prelU,
              __half* __restrict__ agg16P, __half* __restrict__ agg16U) {
    int gid = blockIdx.x * blockDim.x + threadIdx.x;
    int w = gid >> 5;
    int lane = gid & 31;
    if (w >= NPC + NUC) return;
    const int sub = lane & 7;

    const int* col;
    const __half *q, *kt, *vt;
    const float* prel;
    __half* agg16;
    int dN, base, deg;
    if (w < NPC) {
        dN = w;
        base = baseP[dN];
        deg  = degPa[dN];
        col = colP;
        q = projP; kt = projU + DMC; vt = projU + 2 * DMC;
        prel = prelP; agg16 = agg16P;
    } else {
        dN = w - NPC;
        base = baseP[NPC + dN];
        deg  = degPa[NPC + dN];
        col = colP + NEC;
        q = projU; kt = projP + DMC; vt = projP + 2 * DMC;
        prel = prelU; agg16 = agg16U;
    }

    float acc[8] = {0.f, 0.f, 0.f, 0.f, 0.f, 0.f, 0.f, 0.f};
    if (deg > 0) {
        const size_t loff = (size_t)lane * 8;
        float qx[8];
        {
            uint4 uq = *(const uint4*)(q + (size_t)dN * LDPROJ + loff);
            float2 t0 = __half22float2(*(const __half2*)&uq.x);
            float2 t1 = __half22float2(*(const __half2*)&uq.y);
            float2 t2 = __half22float2(*(const __half2*)&uq.z);
            float2 t3 = __half22float2(*(const __half2*)&uq.w);
            qx[0] = t0.x; qx[1] = t0.y; qx[2] = t1.x; qx[3] = t1.y;
            qx[4] = t2.x; qx[5] = t2.y; qx[6] = t3.x; qx[7] = t3.y;
        }
        float pr = prel[lane >> 3] * 0.125f;

        if (deg <= 8) {
            float lg0 = -INFINITY;
            float m = -INFINITY;
            for (int j = 0; j < deg; j++) {
                int s = col[base + j];
                uint4 uk = *(const uint4*)(kt + (size_t)s * LDPROJ + loff);
                float p = dot8(uk, qx);
#pragma unroll
                for (int o = 4; o > 0; o >>= 1) p += __shfl_xor_sync(0xffffffffu, p, o);
                float lg = p * pr;
                if (j == sub) lg0 = lg;
                m = fmaxf(m, lg);
            }
            float e0 = (sub < deg) ? expf(lg0 - m) : 0.0f;
            float tsum = e0;
#pragma unroll
            for (int o = 4; o > 0; o >>= 1) tsum += __shfl_xor_sync(0xffffffffu, tsum, o);
            float inv = 1.0f / (tsum + 1e-16f);
            for (int j = 0; j < deg; j++) {
                float a = __shfl_sync(0xffffffffu, e0, (lane & 24) | j) * inv;
                int s = col[base + j];
                uint4 uv = *(const uint4*)(vt + (size_t)s * LDPROJ + loff);
                float2 v0 = __half22float2(*(const __half2*)&uv.x);
                float2 v1 = __half22float2(*(const __half2*)&uv.y);
                float2 v2 = __half22float2(*(const __half2*)&uv.z);
                float2 v3 = __half22float2(*(const __half2*)&uv.w);
                acc[0] = fmaf(a, v0.x, acc[0]); acc[1] = fmaf(a, v0.y, acc[1]);
                acc[2] = fmaf(a, v1.x, acc[2]); acc[3] = fmaf(a, v1.y, acc[3]);
                acc[4] = fmaf(a, v2.x, acc[4]); acc[5] = fmaf(a, v2.y, acc[5]);
                acc[6] = fmaf(a, v3.x, acc[6]); acc[7] = fmaf(a, v3.y, acc[7]);
            }
        } else {
            float m = -INFINITY;
            for (int j = 0; j < deg; j++) {
                int s = col[base + j];
                uint4 uk = *(const uint4*)(kt + (size_t)s * LDPROJ + loff);
                float p = dot8(uk, qx);
#pragma unroll
                for (int o = 4; o > 0; o >>= 1) p += __shfl_xor_sync(0xffffffffu, p, o);
                m = fmaxf(m, p * pr);
            }
            float ssum = 0.0f;
            for (int j = 0; j < deg; j++) {
                int s = col[base + j];
                uint4 uk = *(const uint4*)(kt + (size_t)s * LDPROJ + loff);
                float p = dot8(uk, qx);
#pragma unroll
                for (int o = 4; o > 0; o >>= 1) p += __shfl_xor_sync(0xffffffffu, p, o);
                ssum += expf(p * pr - m);
            }
            float inv = 1.0f / (ssum + 1e-16f);
            for (int j = 0; j < deg; j++) {
                int s = col[base + j];
                uint4 uk = *(const uint4*)(kt + (size_t)s * LDPROJ + loff);
                float p = dot8(uk, qx);
#pragma unroll
                for (int o = 4; o > 0; o >>= 1) p += __shfl_xor_sync(0xffffffffu, p, o);
                float a = expf(p * pr - m) * inv;
                uint4 uv = *(const uint4*)(vt + (size_t)s * LDPROJ + loff);
                float2 v0 = __half22float2(*(const __half2*)&uv.x);
                float2 v1 = __half22float2(*(const __half2*)&uv.y);
                float2 v2 = __half22float2(*(const __half2*)&uv.z);
                float2 v3 = __half22float2(*(const __half2*)&uv.w);
                acc[0] = fmaf(a, v0.x, acc[0]); acc[1] = fmaf(a, v0.y, acc[1]);
                acc[2] = fmaf(a, v1.x, acc[2]); acc[3] = fmaf(a, v1.y, acc[3]);
                acc[4] = fmaf(a, v2.x, acc[4]); acc[5] = fmaf(a, v2.y, acc[5]);
                acc[6] = fmaf(a, v3.x, acc[6]); acc[7] = fmaf(a, v3.y, acc[7]);
            }
        }
    }
    __half2 h0 = __floats2half2_rn(gelu_f(acc[0]), gelu_f(acc[1]));
    __half2 h1 = __floats2half2_rn(gelu_f(acc[2]), gelu_f(acc[3]));
    __half2 h2 = __floats2half2_rn(gelu_f(acc[4]), gelu_f(acc[5]));
    __half2 h3 = __floats2half2_rn(gelu_f(acc[6]), gelu_f(acc[7]));
    uint4 out = make_uint4(*(uint32_t*)&h0, *(uint32_t*)&h1, *(uint32_t*)&h2, *(uint32_t*)&h3);
    *(uint4*)(agg16 + (size_t)dN * DMC + (size_t)lane * 8) = out;
}

// ---------------------------------------------------------------------------
extern "C" void kernel_launch(void* const* d_in, const int* in_sizes, int n_in,
                              void* d_out, int out_size) {
    (void)in_sizes; (void)n_in; (void)out_size;

    float* base = nullptr;
    cudaGetSymbolAddress((void**)&base, g_buf);

    const int*   user_ids  = (const int*)d_in[0];
    const float* x_product = (const float*)d_in[1];
    const int*   edge_src  = (const int*)d_in[2];
    const int*   edge_dst  = (const int*)d_in[3];
    const float* emb       = (const float*)d_in[4];
    const float* Wk        = (const float*)d_in[5];
    const float* bk        = (const float*)d_in[6];
    const float* Wq        = (const float*)d_in[7];
    const float* bq        = (const float*)d_in[8];
    const float* Wv        = (const float*)d_in[9];
    const float* bv        = (const float*)d_in[10];
    const float* Wout      = (const float*)d_in[11];
    const float* bout      = (const float*)d_in[12];
    const float* skipp     = (const float*)d_in[13];
    const float* arel      = (const float*)d_in[14];
    const float* mrel      = (const float*)d_in[15];
    const float* prel      = (const float*)d_in[16];

    __half* WbigT   = (__half*)(base + OFF_WBIGT);
    float*  bbig    = base + OFF_BBIG;
    __half* WoutT   = (__half*)(base + OFF_WOUTT);
    __half* proj16U = (__half*)(base + H_PROJ16U);
    __half* proj16P = (__half*)(base + H_PROJ16P);
    __half* xu16A   = (__half*)(base + H_XU16A);
    __half* xu16B   = (__half*)(base + H_XU16B);
    __half* xp16A   = (__half*)(base + H_XP16A);
    __half* xp16B   = (__half*)(base + H_XP16B);
    __half* agg16U  = (__half*)(base + H_AGG16U);
    __half* agg16P  = (__half*)(base + H_AGG16P);

    int* ibase = (int*)(base + OFF_INT);
    int* baseP = ibase + I_BASEP;
    int* baseU = ibase + I_BASEU;
    int* degP  = ibase + I_DEGP;
    int* degU  = ibase + I_DEGU;
    int* curP  = ibase + I_CURP;
    int* curU  = ibase + I_CURU;
    int* colP  = ibase + I_COLP;
    int* colU  = ibase + I_COLU;
    int* cnt   = ibase + I_CNT;

    float* out_xu = (float*)d_out;
    float* out_xp = (float*)d_out + SZ_U;

    // 1. Weight assembly
    copyq_kernel<<<dim3(4, 256), 256>>>(Wq, bq, WbigT, bbig);
    fuse_w_kernel<<<dim3(8, 256), 256>>>(Wk, Wv, arel, mrel, WbigT);
    fuse_b_kernel<<<8, 256>>>(bk, bv, arel, mrel, bbig);
    woutT_kernel<<<dim3(4, 256), 256>>>(Wout, WoutT);

    // 2. Merged gather + convert (fp16)
    {
        size_t n = (size_t)(NUC + NPC) * (DMC / 4);
        prep16_kernel<<<(unsigned)((n + 255) / 256), 256>>>(user_ids, emb, x_product,
                                                            xu16A, xp16A);
    }

    // 3. Segment tables
    cudaMemsetAsync(degP, 0, (size_t)(NPC + NUC) * sizeof(int));
    cudaMemsetAsync(cnt, 0, 2 * sizeof(int));
    count_deg<<<(NEC + 255) / 256, 256>>>(edge_src, edge_dst, degP, degU);
    base_kernel<<<(NPC + 255) / 256, 256>>>(degP, baseP, curP, NPC, cnt + 0);
    base_kernel<<<(NUC + 255) / 256, 256>>>(degU, baseU, curU, NUC, cnt + 1);
    build_csr<<<(NEC + 255) / 256, 256>>>(edge_src, edge_dst, curP, curU, colP, colU);

    const int gyU = (NUC + 127) / 128;   // 625
    const int gyP = (NPC + 127) / 128;   // 313
    const unsigned aggBlocks = (unsigned)(((size_t)(NPC + NUC) * 32 + 255) / 256);

    for (int l = 0; l < 2; l++) {
        const __half* xu16_in = l ? xu16B : xu16A;
        const __half* xp16_in = l ? xp16B : xp16A;
        float* xu_out = l ? out_xu : nullptr;
        float* xp_out = l ? out_xp : nullptr;
        __half* xu16_out = l ? nullptr : xu16B;
        __half* xp16_out = l ? nullptr : xp16B;
        int gelu_after = (l == 0) ? 1 : 0;
        size_t cu = (size_t)(l * 2 + 0), cp = (size_t)(l * 2 + 1);

        // Projections: U + P in one launch (fp16 outputs)
        gemm_dual<<<dim3(LDPROJ / 128, gyU + gyP), 256>>>(
            xu16_in, WbigT + cu * LDPROJ * DMC, bbig + cu * LDPROJ,
            nullptr, proj16U, nullptr, nullptr,
            xp16_in, WbigT + cp * LDPROJ * DMC, bbig + cp * LDPROJ,
            nullptr, proj16P, nullptr, nullptr,
            gyU, 0, LDPROJ, 0, 0);

        // Edge attention, both relations in one launch
        agg_dual<<<aggBlocks, 256>>>(baseP, degP, colP, proj16P, proj16U,
                                     prel + (size_t)(l * 2 + 0) * NHC,
                                     prel + (size_t)(l * 2 + 1) * NHC,
                                     agg16P, agg16U);

        // Output GEMMs: U + P in one launch (fp16 skip blend, + gelu for l==0)
        gemm_dual<<<dim3(DMC / 128, gyU + gyP), 256>>>(
            agg16U, WoutT + cu * DMC * DMC, bout + cu * DMC,
            xu_out, xu16_out, xu16_in, skipp + cu,
            agg16P, WoutT + cp * DMC * DMC, bout + cp * DMC,
            xp_out, xp16_out, xp16_in, skipp + cp,
            gyU, DMC, DMC, 1, gelu_after);
    }
}

// round 17
// speedup vs baseline: 1.2641x; 1.0527x over previous
#include <cuda_runtime.h>
#include <cuda_fp16.h>
#include <math.h>
#include <stdint.h>

#define NUC 80000
#define NPC 40000
#define NEC 160000
#define DMC 256
#define NHC 4
#define NDC 64
#define LDPROJ 768

static const size_t SZ_U = (size_t)NUC * DMC;
static const size_t SZ_P = (size_t)NPC * DMC;

// Scratch layout (float units)
static const size_t OFF_WBIGT = 0;                              // fp16 [4][768][256]
static const size_t OFF_BBIG  = OFF_WBIGT + (size_t)4 * LDPROJ * DMC / 2;
static const size_t OFF_WOUTT = OFF_BBIG + 4 * LDPROJ;          // fp16 [4][256][256]
static const size_t OFF_INT   = OFF_WOUTT + (size_t)4 * DMC * DMC / 2;
static const size_t I_BASEP = 0;
static const size_t I_BASEU = I_BASEP + NPC;
static const size_t I_DEGP  = I_BASEU + NUC;
static const size_t I_DEGU  = I_DEGP + NPC;
static const size_t I_CURP  = I_DEGU + NUC;
static const size_t I_CURU  = I_CURP + NPC;
static const size_t I_COLP  = I_CURU + NUC;
static const size_t I_COLU  = I_COLP + NEC;
static const size_t I_CNT   = I_COLU + NEC;
static const size_t N_INTS  = I_CNT + 2;
static const size_t OFF_H     = (OFF_INT + N_INTS + 3) & ~(size_t)3;
static const size_t H_PROJ16U = OFF_H;
static const size_t H_PROJ16P = H_PROJ16U + (size_t)NUC * LDPROJ / 2;
static const size_t H_XU16A   = H_PROJ16P + (size_t)NPC * LDPROJ / 2;
static const size_t H_XU16B   = H_XU16A + SZ_U / 2;
static const size_t H_XP16A   = H_XU16B + SZ_U / 2;
static const size_t H_XP16B   = H_XP16A + SZ_P / 2;
static const size_t H_AGG16U  = H_XP16B + SZ_P / 2;
static const size_t H_AGG16P  = H_AGG16U + SZ_U / 2;
static const size_t TOTAL_F   = H_AGG16P + SZ_P / 2;

__device__ float g_buf[TOTAL_F];

// ---------------------------------------------------------------------------
__device__ __forceinline__ float gelu_f(float x) {
    return 0.5f * x * (1.0f + erff(x * 0.70710678118654752f));
}
__device__ __forceinline__ uint32_t smem_u32(const void* p) {
    return (uint32_t)__cvta_generic_to_shared(p);
}

#define CP_ASYNC16(dst, src, sz) \
    asm volatile("cp.async.cg.shared.global [%0], [%1], 16, %2;" \
                 :: "r"(dst), "l"(src), "r"(sz) : "memory")
#define CP_COMMIT() asm volatile("cp.async.commit_group;" ::: "memory")
#define CP_WAIT0()  asm volatile("cp.async.wait_group 0;" ::: "memory")

#define LDSM4(r0, r1, r2, r3, addr) \
    asm volatile("ldmatrix.sync.aligned.m8n8.x4.shared.b16 {%0,%1,%2,%3}, [%4];" \
                 : "=r"(r0), "=r"(r1), "=r"(r2), "=r"(r3) : "r"(addr))

#define MMA16(d, av, b0v, b1v) \
    asm volatile("mma.sync.aligned.m16n8k16.row.col.f32.f16.f16.f32 " \
                 "{%0,%1,%2,%3}, {%4,%5,%6,%7}, {%8,%9}, {%0,%1,%2,%3};" \
                 : "+f"((d)[0]), "+f"((d)[1]), "+f"((d)[2]), "+f"((d)[3]) \
                 : "r"((av)[0]), "r"((av)[1]), "r"((av)[2]), "r"((av)[3]), \
                   "r"(b0v), "r"(b1v))

// ---------------------------------------------------------------------------
// Weight assembly (fp16, transposed [n][k])
__global__ void copyq_kernel(const float* __restrict__ Wq, const float* __restrict__ bq,
                             __half* __restrict__ WbigT, float* __restrict__ bbig) {
    int c = blockIdx.x, i = blockIdx.y, j = threadIdx.x;
    WbigT[((size_t)c * LDPROJ + j) * DMC + i] =
        __float2half_rn(Wq[(size_t)c * DMC * DMC + (size_t)i * DMC + j]);
    if (i == 0) bbig[(size_t)c * LDPROJ + j] = bq[(size_t)c * DMC + j];
}

__global__ void fuse_w_kernel(const float* __restrict__ Wk, const float* __restrict__ Wv,
                              const float* __restrict__ arel, const float* __restrict__ mrel,
                              __half* __restrict__ WbigT) {
    int c = blockIdx.x, i = blockIdx.y, j = threadIdx.x;
    int kv = c >> 2, lt = c & 3;
    const float* Wsrc = (kv ? Wv : Wk) + (size_t)lt * DMC * DMC;
    const float* R    = (kv ? mrel : arel) + (size_t)lt * NHC * NDC * NDC;
    int h = j >> 6, e = j & 63;
    const float* wrow = Wsrc + (size_t)i * DMC + h * NDC;
    const float* rr   = R + (size_t)h * NDC * NDC + e;
    float sum = 0.0f;
#pragma unroll 8
    for (int d = 0; d < NDC; d++) sum = fmaf(wrow[d], rr[(size_t)d * NDC], sum);
    int n = DMC + kv * DMC + j;
    WbigT[((size_t)lt * LDPROJ + n) * DMC + i] = __float2half_rn(sum);
}

__global__ void fuse_b_kernel(const float* __restrict__ bk, const float* __restrict__ bv,
                              const float* __restrict__ arel, const float* __restrict__ mrel,
                              float* __restrict__ bbig) {
    int c = blockIdx.x, j = threadIdx.x;
    int kv = c >> 2, lt = c & 3;
    const float* bsrc = (kv ? bv : bk) + (size_t)lt * DMC;
    const float* R    = (kv ? mrel : arel) + (size_t)lt * NHC * NDC * NDC;
    int h = j >> 6, e = j & 63;
    float sum = 0.0f;
#pragma unroll 8
    for (int d = 0; d < NDC; d++)
        sum = fmaf(bsrc[h * NDC + d], R[(size_t)h * NDC * NDC + (size_t)d * NDC + e], sum);
    bbig[(size_t)lt * LDPROJ + DMC + kv * DMC + j] = sum;
}

__global__ void woutT_kernel(const float* __restrict__ Wout, __half* __restrict__ WoutT) {
    int c = blockIdx.x, k = blockIdx.y, n = threadIdx.x;
    WoutT[((size_t)c * DMC + n) * DMC + k] =
        __float2half_rn(Wout[(size_t)c * DMC * DMC + (size_t)k * DMC + n]);
}

// ---------------------------------------------------------------------------
__global__ void prep16_kernel(const int* __restrict__ ids, const float* __restrict__ tab,
                              const float* __restrict__ xprod,
                              __half* __restrict__ xu16, __half* __restrict__ xp16) {
    size_t i = (size_t)blockIdx.x * blockDim.x + threadIdx.x;
    const size_t nU = (size_t)NUC * (DMC / 4);
    const size_t nP = (size_t)NPC * (DMC / 4);
    if (i < nU) {
        size_t row = i >> 6;
        int c4 = (int)(i & 63);
        float4 v = ((const float4*)(tab + (size_t)ids[row] * DMC))[c4];
        __half2 h0 = __floats2half2_rn(v.x, v.y);
        __half2 h1 = __floats2half2_rn(v.z, v.w);
        ((uint2*)xu16)[i] = make_uint2(*(uint32_t*)&h0, *(uint32_t*)&h1);
    } else if (i < nU + nP) {
        size_t j = i - nU;
        float4 v = ((const float4*)xprod)[j];
        __half2 h0 = __floats2half2_rn(v.x, v.y);
        __half2 h1 = __floats2half2_rn(v.z, v.w);
        ((uint2*)xp16)[j] = make_uint2(*(uint32_t*)&h0, *(uint32_t*)&h1);
    }
}

// ---------------------------------------------------------------------------
// CSR construction (segment order nondeterministic; segments disjoint & exact)
__global__ void count_deg(const int* __restrict__ src, const int* __restrict__ dst,
                          int* __restrict__ degP, int* __restrict__ degU) {
    int e = blockIdx.x * blockDim.x + threadIdx.x;
    if (e >= NEC) return;
    atomicAdd(&degP[dst[e]], 1);
    atomicAdd(&degU[src[e]], 1);
}

__global__ __launch_bounds__(256)
void base_kernel(const int* __restrict__ deg, int* __restrict__ basearr,
                 int* __restrict__ cursor, int n, int* __restrict__ gcount) {
    __shared__ int wsum[8];
    __shared__ int blockoff;
    int i = blockIdx.x * 256 + threadIdx.x;
    int lane = threadIdx.x & 31, wid = threadIdx.x >> 5;
    int d = (i < n) ? deg[i] : 0;
    int p = d;
#pragma unroll
    for (int o = 1; o < 32; o <<= 1) {
        int u = __shfl_up_sync(0xffffffffu, p, o);
        if (lane >= o) p += u;
    }
    if (lane == 31) wsum[wid] = p;
    __syncthreads();
    if (threadIdx.x == 0) {
        int s = 0;
#pragma unroll
        for (int w = 0; w < 8; w++) { int t = wsum[w]; wsum[w] = s; s += t; }
        blockoff = atomicAdd(gcount, s);
    }
    __syncthreads();
    if (i < n) {
        int excl = blockoff + wsum[wid] + p - d;
        basearr[i] = excl;
        cursor[i] = excl;
    }
}

__global__ void build_csr(const int* __restrict__ src, const int* __restrict__ dst,
                          int* __restrict__ curP, int* __restrict__ curU,
                          int* __restrict__ colP, int* __restrict__ colU) {
    int e = blockIdx.x * blockDim.x + threadIdx.x;
    if (e >= NEC) return;
    int s = src[e], d = dst[e];
    colP[atomicAdd(&curP[d], 1)] = s;
    colU[atomicAdd(&curU[s], 1)] = d;
}

// ---------------------------------------------------------------------------
// FP16 GEMM, DUAL (unchanged from R16)
#define SROW 40
__global__ __launch_bounds__(256, 2)
void gemm_dual(const __half* __restrict__ Au, const __half* __restrict__ Bu,
               const float* __restrict__ biasu, float* __restrict__ Cu,
               __half* __restrict__ C16u, const __half* __restrict__ xoldu,
               const float* __restrict__ skipu,
               const __half* __restrict__ Ap, const __half* __restrict__ Bp,
               const float* __restrict__ biasp, float* __restrict__ Cp,
               __half* __restrict__ C16p, const __half* __restrict__ xoldp,
               const float* __restrict__ skipp_,
               int gyU, int ldc, int ldc16, int mode, int gelu_after) {
    __shared__ __half sA[2][128 * SROW];
    __shared__ __half sB[2][128 * SROW];

    const __half *A16, *BT;
    const float* bias;
    float* C;
    __half* C16;
    const __half* xold16;
    const float* skipPtr;
    int Mtot, bm;
    if ((int)blockIdx.y < gyU) {
        A16 = Au; BT = Bu; bias = biasu; C = Cu; C16 = C16u;
        xold16 = xoldu; skipPtr = skipu;
        Mtot = NUC; bm = blockIdx.y * 128;
    } else {
        A16 = Ap; BT = Bp; bias = biasp; C = Cp; C16 = C16p;
        xold16 = xoldp; skipPtr = skipp_;
        Mtot = NPC; bm = (blockIdx.y - gyU) * 128;
    }

    const int t = threadIdx.x;
    const int lane = t & 31;
    const int warp = t >> 5;
    const int wm = warp & 3;
    const int wn = warp >> 2;
    const int bn = blockIdx.x * 128;

    const int lr_ = t >> 2, lc_ = t & 3;
    const __half* gA0 = A16 + (size_t)(bm + lr_) * DMC + lc_ * 8;
    const __half* gA1 = A16 + (size_t)(bm + lr_ + 64) * DMC + lc_ * 8;
    const __half* gB0 = BT + (size_t)(bn + lr_) * DMC + lc_ * 8;
    const __half* gB1 = BT + (size_t)(bn + lr_ + 64) * DMC + lc_ * 8;
    const uint32_t szA0 = (bm + lr_ < Mtot) ? 16u : 0u;
    const uint32_t szA1 = (bm + lr_ + 64 < Mtot) ? 16u : 0u;
    uint32_t dA0[2], dA1[2], dB0[2], dB1[2];
#pragma unroll
    for (int b = 0; b < 2; b++) {
        dA0[b] = smem_u32(&sA[b][lr_ * SROW + lc_ * 8]);
        dA1[b] = smem_u32(&sA[b][(lr_ + 64) * SROW + lc_ * 8]);
        dB0[b] = smem_u32(&sB[b][lr_ * SROW + lc_ * 8]);
        dB1[b] = smem_u32(&sB[b][(lr_ + 64) * SROW + lc_ * 8]);
    }

    const int a_row = (lane & 7) + ((lane >> 3) & 1) * 8;
    const int a_ch  = ((lane >> 4) & 1) * 8;
    const int b_row = (lane & 7) + ((lane >> 4) & 1) * 8;
    const int b_ch  = ((lane >> 3) & 1) * 8;

    float acc[2][8][4];
#pragma unroll
    for (int mi = 0; mi < 2; mi++)
#pragma unroll
        for (int ni = 0; ni < 8; ni++)
#pragma unroll
            for (int r = 0; r < 4; r++) acc[mi][ni][r] = 0.0f;

    CP_ASYNC16(dA0[0], gA0, szA0);
    CP_ASYNC16(dA1[0], gA1, szA1);
    CP_ASYNC16(dB0[0], gB0, 16u);
    CP_ASYNC16(dB1[0], gB1, 16u);
    CP_COMMIT();

    for (int i = 0; i < 8; i++) {
        CP_WAIT0();
        __syncthreads();
        if (i < 7) {
            const int kn = (i + 1) * 32;
            const int nb = (i + 1) & 1;
            CP_ASYNC16(dA0[nb], gA0 + kn, szA0);
            CP_ASYNC16(dA1[nb], gA1 + kn, szA1);
            CP_ASYNC16(dB0[nb], gB0 + kn, 16u);
            CP_ASYNC16(dB1[nb], gB1 + kn, 16u);
            CP_COMMIT();
        }
        const int cb = i & 1;
#pragma unroll
        for (int ks = 0; ks < 2; ks++) {
            uint32_t a[2][4], b[8][2];
#pragma unroll
            for (int mi = 0; mi < 2; mi++) {
                uint32_t addr = smem_u32(&sA[cb][(wm * 32 + mi * 16 + a_row) * SROW + ks * 16 + a_ch]);
                LDSM4(a[mi][0], a[mi][1], a[mi][2], a[mi][3], addr);
            }
#pragma unroll
            for (int n2 = 0; n2 < 4; n2++) {
                uint32_t addr = smem_u32(&sB[cb][(wn * 64 + n2 * 16 + b_row) * SROW + ks * 16 + b_ch]);
                LDSM4(b[2 * n2][0], b[2 * n2][1], b[2 * n2 + 1][0], b[2 * n2 + 1][1], addr);
            }
#pragma unroll
            for (int mi = 0; mi < 2; mi++)
#pragma unroll
                for (int ni = 0; ni < 8; ni++)
                    MMA16(acc[mi][ni], a[mi], b[ni][0], b[ni][1]);
        }
    }

    float beta = 1.0f, omb = 0.0f;
    if (mode == 1) {
        float sv = *skipPtr;
        beta = 1.0f / (1.0f + expf(-sv));
        omb = 1.0f - beta;
    }

    const int rg = lane >> 2;
    const int cg = (lane & 3) * 2;
#pragma unroll
    for (int mi = 0; mi < 2; mi++) {
#pragma unroll
        for (int ni = 0; ni < 8; ni++) {
            int col = bn + wn * 64 + ni * 8 + cg;
            float2 bb = *(const float2*)(bias + col);
#pragma unroll
            for (int half = 0; half < 2; half++) {
                int row = bm + wm * 32 + mi * 16 + rg + half * 8;
                if (row >= Mtot) continue;
                float v0 = acc[mi][ni][half * 2 + 0] + bb.x;
                float v1 = acc[mi][ni][half * 2 + 1] + bb.y;
                if (mode == 1) {
                    float2 xo = __half22float2(
                        *(const __half2*)(xold16 + (size_t)row * DMC + col));
                    v0 = beta * v0 + omb * xo.x;
                    v1 = beta * v1 + omb * xo.y;
                }
                if (gelu_after) { v0 = gelu_f(v0); v1 = gelu_f(v1); }
                if (C)
                    *(float2*)(C + (size_t)row * ldc + col) = make_float2(v0, v1);
                if (C16) {
                    __half2 hv = __floats2half2_rn(v0, v1);
                    *(uint32_t*)(C16 + (size_t)row * ldc16 + col) = *(uint32_t*)&hv;
                }
            }
        }
    }
}

// ---------------------------------------------------------------------------
// Fused edge attention, one warp per dst, 4 heads in-warp, dual-relation.
// Fast path: 2-deep software pipeline (next neighbor's col+load issued before
// consuming current) in both the logits and accumulate passes.
__device__ __forceinline__ float dot8(const uint4& ua, const float* qx) {
    float2 a0 = __half22float2(*(const __half2*)&ua.x);
    float2 a1 = __half22float2(*(const __half2*)&ua.y);
    float2 a2 = __half22float2(*(const __half2*)&ua.z);
    float2 a3 = __half22float2(*(const __half2*)&ua.w);
    float p = qx[0] * a0.x + qx[1] * a0.y;
    p = fmaf(qx[2], a1.x, p); p = fmaf(qx[3], a1.y, p);
    p = fmaf(qx[4], a2.x, p); p = fmaf(qx[5], a2.y, p);
    p = fmaf(qx[6], a3.x, p); p = fmaf(qx[7], a3.y, p);
    return p;
}

__global__ __launch_bounds__(256)
void agg_dual(const int* __restrict__ baseP, const int* __restrict__ degPa,
              const int* __restrict__ colP,
              const __half* __restrict__ projP, const __half* __restrict__ projU,
              const float* __restrict__ prelP, const float* __restrict__ prelU,
              __half* __restrict__ agg16P, __half* __restrict__ agg16U) {
    int gid = blockIdx.x * blockDim.x + threadIdx.x;
    int w = gid >> 5;
    int lane = gid & 31;
    if (w >= NPC + NUC) return;
    const int sub = lane & 7;

    const int* col;
    const __half *q, *kt, *vt;
    const float* prel;
    __half* agg16;
    int dN, base, deg;
    if (w < NPC) {
        dN = w;
        base = baseP[dN];
        deg  = degPa[dN];
        col = colP;
        q = projP; kt = projU + DMC; vt = projU + 2 * DMC;
        prel = prelP; agg16 = agg16P;
    } else {
        dN = w - NPC;
        base = baseP[NPC + dN];
        deg  = degPa[NPC + dN];
        col = colP + NEC;
        q = projU; kt = projP + DMC; vt = projP + 2 * DMC;
        prel = prelU; agg16 = agg16U;
    }

    float acc[8] = {0.f, 0.f, 0.f, 0.f, 0.f, 0.f, 0.f, 0.f};
    if (deg > 0) {
        const size_t loff = (size_t)lane * 8;
        float qx[8];
        {
            uint4 uq = *(const uint4*)(q + (size_t)dN * LDPROJ + loff);
            float2 t0 = __half22float2(*(const __half2*)&uq.x);
            float2 t1 = __half22float2(*(const __half2*)&uq.y);
            float2 t2 = __half22float2(*(const __half2*)&uq.z);
            float2 t3 = __half22float2(*(const __half2*)&uq.w);
            qx[0] = t0.x; qx[1] = t0.y; qx[2] = t1.x; qx[3] = t1.y;
            qx[4] = t2.x; qx[5] = t2.y; qx[6] = t3.x; qx[7] = t3.y;
        }
        float pr = prel[lane >> 3] * 0.125f;

        if (deg <= 8) {
            // ---- logits pass, 2-deep pipeline ----
            float lg0 = -INFINITY;
            float m = -INFINITY;
            uint4 uk0 = *(const uint4*)(kt + (size_t)col[base] * LDPROJ + loff);
            for (int j = 0; j < deg; j++) {
                uint4 uk1;
                if (j + 1 < deg)
                    uk1 = *(const uint4*)(kt + (size_t)col[base + j + 1] * LDPROJ + loff);
                float p = dot8(uk0, qx);
#pragma unroll
                for (int o = 4; o > 0; o >>= 1) p += __shfl_xor_sync(0xffffffffu, p, o);
                float lg = p * pr;
                if (j == sub) lg0 = lg;
                m = fmaxf(m, lg);
                uk0 = uk1;
            }
            float e0 = (sub < deg) ? expf(lg0 - m) : 0.0f;
            float tsum = e0;
#pragma unroll
            for (int o = 4; o > 0; o >>= 1) tsum += __shfl_xor_sync(0xffffffffu, tsum, o);
            float inv = 1.0f / (tsum + 1e-16f);
            // ---- accumulate pass, 2-deep pipeline ----
            uint4 uv0 = *(const uint4*)(vt + (size_t)col[base] * LDPROJ + loff);
            for (int j = 0; j < deg; j++) {
                uint4 uv1;
                if (j + 1 < deg)
                    uv1 = *(const uint4*)(vt + (size_t)col[base + j + 1] * LDPROJ + loff);
                float a = __shfl_sync(0xffffffffu, e0, (lane & 24) | j) * inv;
                float2 v0 = __half22float2(*(const __half2*)&uv0.x);
                float2 v1 = __half22float2(*(const __half2*)&uv0.y);
                float2 v2 = __half22float2(*(const __half2*)&uv0.z);
                float2 v3 = __half22float2(*(const __half2*)&uv0.w);
                acc[0] = fmaf(a, v0.x, acc[0]); acc[1] = fmaf(a, v0.y, acc[1]);
                acc[2] = fmaf(a, v1.x, acc[2]); acc[3] = fmaf(a, v1.y, acc[3]);
                acc[4] = fmaf(a, v2.x, acc[4]); acc[5] = fmaf(a, v2.y, acc[5]);
                acc[6] = fmaf(a, v3.x, acc[6]); acc[7] = fmaf(a, v3.y, acc[7]);
                uv0 = uv1;
            }
        } else {
            // recompute path (any degree)
            float m = -INFINITY;
            for (int j = 0; j < deg; j++) {
                int s = col[base + j];
                uint4 uk = *(const uint4*)(kt + (size_t)s * LDPROJ + loff);
                float p = dot8(uk, qx);
#pragma unroll
                for (int o = 4; o > 0; o >>= 1) p += __shfl_xor_sync(0xffffffffu, p, o);
                m = fmaxf(m, p * pr);
            }
            float ssum = 0.0f;
            for (int j = 0; j < deg; j++) {
                int s = col[base + j];
                uint4 uk = *(const uint4*)(kt + (size_t)s * LDPROJ + loff);
                float p = dot8(uk, qx);
#pragma unroll
                for (int o = 4; o > 0; o >>= 1) p += __shfl_xor_sync(0xffffffffu, p, o);
                ssum += expf(p * pr - m);
            }
            float inv = 1.0f / (ssum + 1e-16f);
            for (int j = 0; j < deg; j++) {
                int s = col[base + j];
                uint4 uk = *(const uint4*)(kt + (size_t)s * LDPROJ + loff);
                float p = dot8(uk, qx);
#pragma unroll
                for (int o = 4; o > 0; o >>= 1) p += __shfl_xor_sync(0xffffffffu, p, o);
                float a = expf(p * pr - m) * inv;
                uint4 uv = *(const uint4*)(vt + (size_t)s * LDPROJ + loff);
                float2 v0 = __half22float2(*(const __half2*)&uv.x);
                float2 v1 = __half22float2(*(const __half2*)&uv.y);
                float2 v2 = __half22float2(*(const __half2*)&uv.z);
                float2 v3 = __half22float2(*(const __half2*)&uv.w);
                acc[0] = fmaf(a, v0.x, acc[0]); acc[1] = fmaf(a, v0.y, acc[1]);
                acc[2] = fmaf(a, v1.x, acc[2]); acc[3] = fmaf(a, v1.y, acc[3]);
                acc[4] = fmaf(a, v2.x, acc[4]); acc[5] = fmaf(a, v2.y, acc[5]);
                acc[6] = fmaf(a, v3.x, acc[6]); acc[7] = fmaf(a, v3.y, acc[7]);
            }
        }
    }
    __half2 h0 = __floats2half2_rn(gelu_f(acc[0]), gelu_f(acc[1]));
    __half2 h1 = __floats2half2_rn(gelu_f(acc[2]), gelu_f(acc[3]));
    __half2 h2 = __floats2half2_rn(gelu_f(acc[4]), gelu_f(acc[5]));
    __half2 h3 = __floats2half2_rn(gelu_f(acc[6]), gelu_f(acc[7]));
    uint4 out = make_uint4(*(uint32_t*)&h0, *(uint32_t*)&h1, *(uint32_t*)&h2, *(uint32_t*)&h3);
    *(uint4*)(agg16 + (size_t)dN * DMC + (size_t)lane * 8) = out;
}

// ---------------------------------------------------------------------------
extern "C" void kernel_launch(void* const* d_in, const int* in_sizes, int n_in,
                              void* d_out, int out_size) {
    (void)in_sizes; (void)n_in; (void)out_size;

    float* base = nullptr;
    cudaGetSymbolAddress((void**)&base, g_buf);

    const int*   user_ids  = (const int*)d_in[0];
    const float* x_product = (const float*)d_in[1];
    const int*   edge_src  = (const int*)d_in[2];
    const int*   edge_dst  = (const int*)d_in[3];
    const float* emb       = (const float*)d_in[4];
    const float* Wk        = (const float*)d_in[5];
    const float* bk        = (const float*)d_in[6];
    const float* Wq        = (const float*)d_in[7];
    const float* bq        = (const float*)d_in[8];
    const float* Wv        = (const float*)d_in[9];
    const float* bv        = (const float*)d_in[10];
    const float* Wout      = (const float*)d_in[11];
    const float* bout      = (const float*)d_in[12];
    const float* skipp     = (const float*)d_in[13];
    const float* arel      = (const float*)d_in[14];
    const float* mrel      = (const float*)d_in[15];
    const float* prel      = (const float*)d_in[16];

    __half* WbigT   = (__half*)(base + OFF_WBIGT);
    float*  bbig    = base + OFF_BBIG;
    __half* WoutT   = (__half*)(base + OFF_WOUTT);
    __half* proj16U = (__half*)(base + H_PROJ16U);
    __half* proj16P = (__half*)(base + H_PROJ16P);
    __half* xu16A   = (__half*)(base + H_XU16A);
    __half* xu16B   = (__half*)(base + H_XU16B);
    __half* xp16A   = (__half*)(base + H_XP16A);
    __half* xp16B   = (__half*)(base + H_XP16B);
    __half* agg16U  = (__half*)(base + H_AGG16U);
    __half* agg16P  = (__half*)(base + H_AGG16P);

    int* ibase = (int*)(base + OFF_INT);
    int* baseP = ibase + I_BASEP;
    int* baseU = ibase + I_BASEU;
    int* degP  = ibase + I_DEGP;
    int* degU  = ibase + I_DEGU;
    int* curP  = ibase + I_CURP;
    int* curU  = ibase + I_CURU;
    int* colP  = ibase + I_COLP;
    int* colU  = ibase + I_COLU;
    int* cnt   = ibase + I_CNT;

    float* out_xu = (float*)d_out;
    float* out_xp = (float*)d_out + SZ_U;

    // 1. Weight assembly
    copyq_kernel<<<dim3(4, 256), 256>>>(Wq, bq, WbigT, bbig);
    fuse_w_kernel<<<dim3(8, 256), 256>>>(Wk, Wv, arel, mrel, WbigT);
    fuse_b_kernel<<<8, 256>>>(bk, bv, arel, mrel, bbig);
    woutT_kernel<<<dim3(4, 256), 256>>>(Wout, WoutT);

    // 2. Merged gather + convert (fp16)
    {
        size_t n = (size_t)(NUC + NPC) * (DMC / 4);
        prep16_kernel<<<(unsigned)((n + 255) / 256), 256>>>(user_ids, emb, x_product,
                                                            xu16A, xp16A);
    }

    // 3. Segment tables
    cudaMemsetAsync(degP, 0, (size_t)(NPC + NUC) * sizeof(int));
    cudaMemsetAsync(cnt, 0, 2 * sizeof(int));
    count_deg<<<(NEC + 255) / 256, 256>>>(edge_src, edge_dst, degP, degU);
    base_kernel<<<(NPC + 255) / 256, 256>>>(degP, baseP, curP, NPC, cnt + 0);
    base_kernel<<<(NUC + 255) / 256, 256>>>(degU, baseU, curU, NUC, cnt + 1);
    build_csr<<<(NEC + 255) / 256, 256>>>(edge_src, edge_dst, curP, curU, colP, colU);

    const int gyU = (NUC + 127) / 128;
    const int gyP = (NPC + 127) / 128;
    const unsigned aggBlocks = (unsigned)(((size_t)(NPC + NUC) * 32 + 255) / 256);

    for (int l = 0; l < 2; l++) {
        const __half* xu16_in = l ? xu16B : xu16A;
        const __half* xp16_in = l ? xp16B : xp16A;
        float* xu_out = l ? out_xu : nullptr;
        float* xp_out = l ? out_xp : nullptr;
        __half* xu16_out = l ? nullptr : xu16B;
        __half* xp16_out = l ? nullptr : xp16B;
        int gelu_after = (l == 0) ? 1 : 0;
        size_t cu = (size_t)(l * 2 + 0), cp = (size_t)(l * 2 + 1);

        // Projections: U + P in one launch (fp16 outputs)
        gemm_dual<<<dim3(LDPROJ / 128, gyU + gyP), 256>>>(
            xu16_in, WbigT + cu * LDPROJ * DMC, bbig + cu * LDPROJ,
            nullptr, proj16U, nullptr, nullptr,
            xp16_in, WbigT + cp * LDPROJ * DMC, bbig + cp * LDPROJ,
            nullptr, proj16P, nullptr, nullptr,
            gyU, 0, LDPROJ, 0, 0);

        // Edge attention, both relations in one launch
        agg_dual<<<aggBlocks, 256>>>(baseP, degP, colP, proj16P, proj16U,
                                     prel + (size_t)(l * 2 + 0) * NHC,
                                     prel + (size_t)(l * 2 + 1) * NHC,
                                     agg16P, agg16U);

        // Output GEMMs: U + P in one launch (fp16 skip blend, + gelu for l==0)
        gemm_dual<<<dim3(DMC / 128, gyU + gyP), 256>>>(
            agg16U, WoutT + cu * DMC * DMC, bout + cu * DMC,
            xu_out, xu16_out, xu16_in, skipp + cu,
            agg16P, WoutT + cp * DMC * DMC, bout + cp * DMC,
            xp_out, xp16_out, xp16_in, skipp + cp,
            gyU, DMC, DMC, 1, gelu_after);
    }
}